// round 6
// baseline (speedup 1.0000x reference)
#include <cuda_runtime.h>
#include <cstdint>
#include <math.h>

#define Bb   8
#define Ss   1024
#define Dd   768
#define Hh   12
#define HDd  64
#define Ll   6
#define DFf  3072
#define Cc   2
#define Mrows (Bb*Ss)      /* 8192 */
#define QKVN  (3*Dd)       /* 2304 */
#define LN_EPS 1e-5f

// ---------------- scratch (device globals: allocation-free) ----------------
__device__ float g_x[Mrows*Dd];
__device__ float g_h[Mrows*Dd];
__device__ float g_qkv[Mrows*QKVN];
__device__ float g_att[Mrows*Dd];
__device__ float g_ff[Mrows*DFf];
__device__ float g_wt[DFf*Dd];     // transposed weight scratch (max 3072*768)

// ======================= helpers =======================
__device__ __forceinline__ uint32_t smem_to_u32(const void* p) {
    uint32_t a;
    asm("{ .reg .u64 t; cvta.to.shared.u64 t, %1; cvt.u32.u64 %0, t; }" : "=r"(a) : "l"(p));
    return a;
}
__device__ __forceinline__ float rna_tf32(float v) {
    asm("cvt.rna.tf32.f32 %0, %0;" : "+f"(v));
    return v;
}
#define CP_ASYNC16(dst, src) \
    asm volatile("cp.async.cg.shared.global [%0], [%1], 16;" :: "r"(dst), "l"(src) : "memory")
#define CP_COMMIT() asm volatile("cp.async.commit_group;" ::: "memory")
#define CP_WAIT0()  asm volatile("cp.async.wait_group 0;" ::: "memory")

__device__ __forceinline__ void mma_tf32(float* d, const uint32_t* a, const uint32_t* b) {
    asm volatile(
        "mma.sync.aligned.m16n8k8.row.col.f32.tf32.tf32.f32 "
        "{%0,%1,%2,%3}, {%4,%5,%6,%7}, {%8,%9}, {%0,%1,%2,%3};"
        : "+f"(d[0]), "+f"(d[1]), "+f"(d[2]), "+f"(d[3])
        : "r"(a[0]), "r"(a[1]), "r"(a[2]), "r"(a[3]), "r"(b[0]), "r"(b[1]));
}

// ---------------- embed ----------------
__global__ void embed_kernel(const int* __restrict__ ids,
                             const float* __restrict__ tok,
                             const float* __restrict__ pos,
                             float* __restrict__ x)
{
    const float sc = 27.712812921102035f; // sqrt(768)
    int i = blockIdx.x * blockDim.x + threadIdx.x;
    int total = Mrows * (Dd / 4);
    if (i >= total) return;
    int row = i / (Dd / 4);
    int c4  = i - row * (Dd / 4);
    int s   = row & (Ss - 1);
    int id  = ids[row];
    const float4* t4 = (const float4*)tok;
    const float4* p4 = (const float4*)pos;
    float4 tv = t4[(size_t)id * (Dd/4) + c4];
    float4 pv = p4[(size_t)s  * (Dd/4) + c4];
    float4 o;
    o.x = (tv.x + pv.x) * sc;
    o.y = (tv.y + pv.y) * sc;
    o.z = (tv.z + pv.z) * sc;
    o.w = (tv.w + pv.w) * sc;
    ((float4*)x)[i] = o;
}

// ---------------- block reduce ----------------
__device__ __forceinline__ void blockReduce2(float& a, float& b, float* buf)
{
    #pragma unroll
    for (int o = 16; o; o >>= 1) {
        a += __shfl_xor_sync(0xffffffffu, a, o);
        b += __shfl_xor_sync(0xffffffffu, b, o);
    }
    int w = threadIdx.x >> 5;
    if ((threadIdx.x & 31) == 0) { buf[w] = a; buf[8 + w] = b; }
    __syncthreads();
    a = 0.f; b = 0.f;
    #pragma unroll
    for (int i = 0; i < 8; i++) { a += buf[i]; b += buf[8 + i]; }
    __syncthreads();
}

// ---------------- layernorm (outputs RNA-rounded to tf32: feeds GEMM A) ----
__global__ __launch_bounds__(256)
void ln_kernel(const float* __restrict__ x,
               const float* __restrict__ gs,
               const float* __restrict__ gb,
               float* __restrict__ out)
{
    __shared__ float buf[16];
    int row = blockIdx.x;
    int t = threadIdx.x;
    const float* xr = x + (size_t)row * Dd;
    float v0 = xr[t], v1 = xr[t + 256], v2 = xr[t + 512];
    float sum = v0 + v1 + v2;
    float sq  = v0*v0 + v1*v1 + v2*v2;
    blockReduce2(sum, sq, buf);
    float mean = sum * (1.0f / Dd);
    float var  = sq * (1.0f / Dd) - mean * mean;
    float rstd = rsqrtf(var + LN_EPS);
    float* orow = out + (size_t)row * Dd;
    orow[t]       = rna_tf32((v0 - mean) * rstd * gs[t]       + gb[t]);
    orow[t + 256] = rna_tf32((v1 - mean) * rstd * gs[t + 256] + gb[t + 256]);
    orow[t + 512] = rna_tf32((v2 - mean) * rstd * gs[t + 512] + gb[t + 512]);
}

// ---------------- weight transpose + RNA round: Wt[N,K] = rna(W[K,N]^T) ----
__global__ __launch_bounds__(256)
void transpose_rna_kernel(const float* __restrict__ W, float* __restrict__ Wt, int K, int N)
{
    __shared__ float t[32][33];
    int n0 = blockIdx.x * 32, k0 = blockIdx.y * 32;
    int x = threadIdx.x & 31, y = threadIdx.x >> 5; // 32x8
    #pragma unroll
    for (int i = 0; i < 32; i += 8)
        t[y + i][x] = W[(size_t)(k0 + y + i) * N + n0 + x];
    __syncthreads();
    #pragma unroll
    for (int i = 0; i < 32; i += 8)
        Wt[(size_t)(n0 + y + i) * K + k0 + x] = rna_tf32(t[x][y + i]);
}

// ---------------- tf32 mma.sync GEMM v3: 128x256 block, warp tile 64x64 ----
// C[M,N] = A[M,K] @ Bt[N,K]^T (+bias)(+res)(relu?)(rnaOut?)
// BM=128, BN=256, BK=32, 256 threads (8 warps, 2x4 grid, warp 64x64),
// 2-stage cp.async, rows padded to 40 floats. Crossbar: 96 B/mma.
// k-permutation trick: fragment slots (qd, qd+4) carry natural k (2qd, 2qd+1).
#define GP 40
#define ASZ (128*GP)                 /* 5120 floats */
#define BSZ (256*GP)                 /* 10240 floats */
#define STG (ASZ+BSZ)                /* 15360 floats per stage */
#define GEMM_SMEM (2*STG*4)          /* 122880 bytes */

template<int K>
__global__ __launch_bounds__(256, 1)
void mma_gemm(const float* __restrict__ A, const float* __restrict__ Bt,
              const float* __restrict__ bias, const float* __restrict__ res,
              float* __restrict__ C, int N, int relu, int rnaOut)
{
    extern __shared__ float smf[];
    uint32_t sb = smem_to_u32(smf);
    int tid = threadIdx.x, lane = tid & 31, wid = tid >> 5;
    int rq = lane >> 2, qd = lane & 3;
    int warpM = (wid >> 2) * 64, warpN = (wid & 3) * 64;
    int m0 = blockIdx.y * 128, n0 = blockIdx.x * 256;
    const float* Abase = A  + (size_t)m0 * K;
    const float* Bbase = Bt + (size_t)n0 * K;
    int lrow  = tid >> 1;        // 0..127
    int lhalf = (tid & 1) * 16;  // float offset within a 32-float row
    constexpr int KI = K >> 5;

    float acc[4][8][4];
    #pragma unroll
    for (int mt = 0; mt < 4; mt++)
        #pragma unroll
        for (int nt = 0; nt < 8; nt++)
            #pragma unroll
            for (int r = 0; r < 4; r++) acc[mt][nt][r] = 0.f;

    // A: 128 rows x 32 floats, B: 256 rows x 32 floats
    #define ISSUE_STAGE(I) do {                                                   \
        int _st = (I) & 1;                                                         \
        int _k0 = (I) << 5;                                                        \
        uint32_t _dA = sb + (uint32_t)(_st * STG + lrow * GP + lhalf) * 4u;        \
        const float* _sA = Abase + (size_t)lrow * K + _k0 + lhalf;                 \
        CP_ASYNC16(_dA + 0,  _sA + 0);  CP_ASYNC16(_dA + 16, _sA + 4);             \
        CP_ASYNC16(_dA + 32, _sA + 8);  CP_ASYNC16(_dA + 48, _sA + 12);            \
        uint32_t _dB = sb + (uint32_t)(_st * STG + ASZ + lrow * GP + lhalf) * 4u;  \
        const float* _sB = Bbase + (size_t)lrow * K + _k0 + lhalf;                 \
        CP_ASYNC16(_dB + 0,  _sB + 0);  CP_ASYNC16(_dB + 16, _sB + 4);             \
        CP_ASYNC16(_dB + 32, _sB + 8);  CP_ASYNC16(_dB + 48, _sB + 12);            \
        uint32_t _dB2 = _dB + (uint32_t)(128 * GP) * 4u;                           \
        const float* _sB2 = _sB + (size_t)128 * K;                                 \
        CP_ASYNC16(_dB2 + 0,  _sB2 + 0);  CP_ASYNC16(_dB2 + 16, _sB2 + 4);         \
        CP_ASYNC16(_dB2 + 32, _sB2 + 8);  CP_ASYNC16(_dB2 + 48, _sB2 + 12);        \
    } while (0)

    ISSUE_STAGE(0); CP_COMMIT();

    int aoff = (warpM + rq) * GP + 2 * qd;
    int boff = (warpN + rq) * GP + 2 * qd;

    for (int i = 0; i < KI; i++) {
        CP_WAIT0();
        __syncthreads();
        if (i + 1 < KI) { ISSUE_STAGE(i + 1); CP_COMMIT(); }

        const float* As = smf + (i & 1) * STG;
        const float* Bs = As + ASZ;

        #pragma unroll
        for (int ks = 0; ks < 4; ks++) {
            uint32_t a[4][4];
            #pragma unroll
            for (int mt = 0; mt < 4; mt++) {
                float2 x0 = *(const float2*)(As + aoff + ks * 8 + mt * 16 * GP);
                float2 x1 = *(const float2*)(As + aoff + ks * 8 + mt * 16 * GP + 8 * GP);
                a[mt][0] = __float_as_uint(x0.x);
                a[mt][1] = __float_as_uint(x1.x);
                a[mt][2] = __float_as_uint(x0.y);
                a[mt][3] = __float_as_uint(x1.y);
            }
            uint32_t b[8][2];
            #pragma unroll
            for (int nt = 0; nt < 8; nt++) {
                float2 y = *(const float2*)(Bs + boff + ks * 8 + nt * 8 * GP);
                b[nt][0] = __float_as_uint(y.x);
                b[nt][1] = __float_as_uint(y.y);
            }
            #pragma unroll
            for (int mt = 0; mt < 4; mt++)
                #pragma unroll
                for (int nt = 0; nt < 8; nt++)
                    mma_tf32(acc[mt][nt], a[mt], b[nt]);
        }
    }

    // epilogue
    #pragma unroll
    for (int mt = 0; mt < 4; mt++) {
        int r0 = m0 + warpM + mt * 16 + rq;
        #pragma unroll
        for (int nt = 0; nt < 8; nt++) {
            int c0 = n0 + warpN + nt * 8 + qd * 2;
            float2 bv = *(const float2*)(bias + c0);
            float v0 = acc[mt][nt][0] + bv.x;
            float v1 = acc[mt][nt][1] + bv.y;
            float v2 = acc[mt][nt][2] + bv.x;
            float v3 = acc[mt][nt][3] + bv.y;
            if (res) {
                float2 q1 = *(const float2*)(res + (size_t)r0 * N + c0);
                float2 q2 = *(const float2*)(res + (size_t)(r0 + 8) * N + c0);
                v0 += q1.x; v1 += q1.y; v2 += q2.x; v3 += q2.y;
            }
            if (relu) {
                v0 = fmaxf(v0, 0.f); v1 = fmaxf(v1, 0.f);
                v2 = fmaxf(v2, 0.f); v3 = fmaxf(v3, 0.f);
            }
            if (rnaOut) {
                v0 = rna_tf32(v0); v1 = rna_tf32(v1);
                v2 = rna_tf32(v2); v3 = rna_tf32(v3);
            }
            float2 o1; o1.x = v0; o1.y = v1;
            float2 o2; o2.x = v2; o2.y = v3;
            *(float2*)(C + (size_t)r0 * N + c0)       = o1;
            *(float2*)(C + (size_t)(r0 + 8) * N + c0) = o2;
        }
    }
}

// ---------------- tensor-core flash attention (float2 pair-k frags) -------
// grid (S/128, H, B), 256 threads = 8 warps, warp w owns q-rows [16w,16w+16).
#define AT_QP 72
#define AT_KP 72
#define AT_VP 68
#define AT_PP 72
#define ATT_SMEM ((128*AT_QP + 64*AT_KP + 64*AT_VP + 128*AT_PP + 64) * 4)

__global__ __launch_bounds__(256, 2)
void attn_mma_kernel(const float* __restrict__ qkv,
                     const int* __restrict__ mask,
                     float* __restrict__ att)
{
    extern __shared__ float sa[];
    float* Qs = sa;                    // [128][72]
    float* Ks = Qs + 128 * AT_QP;      // [64][72]
    float* Vs = Ks + 64 * AT_KP;       // [64][68]
    float* Ps = Vs + 64 * AT_VP;       // [128][72]
    float* mk = Ps + 128 * AT_PP;      // [64]

    int qb = blockIdx.x, h = blockIdx.y, b = blockIdx.z;
    int tid = threadIdx.x, lane = tid & 31, wid = tid >> 5;
    int rq = lane >> 2, qd = lane & 3;
    int warpM = wid * 16;
    int base_q = b * Ss + qb * 128;

    // load Q tile: scale 1/8 (exact), RNA round
    const float* qsrc = qkv + (size_t)base_q * QKVN + h * 192;
    #pragma unroll
    for (int it = 0; it < 8; it++) {
        int idx = it * 256 + tid;           // 2048 float4 = 128 rows x 16
        int r = idx >> 4, c4 = idx & 15;
        float4 v = *(const float4*)(qsrc + (size_t)r * QKVN + c4 * 4);
        float* dst = Qs + r * AT_QP + c4 * 4;
        dst[0] = rna_tf32(v.x * 0.125f);
        dst[1] = rna_tf32(v.y * 0.125f);
        dst[2] = rna_tf32(v.z * 0.125f);
        dst[3] = rna_tf32(v.w * 0.125f);
    }

    float oacc[8][4];
    #pragma unroll
    for (int nt = 0; nt < 8; nt++)
        #pragma unroll
        for (int r = 0; r < 4; r++) oacc[nt][r] = 0.f;
    float m0 = -1e30f, m1 = -1e30f, l0 = 0.f, l1 = 0.f;

    __syncthreads();   // Q ready

    for (int kt = 0; kt < Ss / 64; kt++) {
        if (kt) __syncthreads();   // previous PV reads of Vs done
        const float* ksrc = qkv + (size_t)(b * Ss + kt * 64) * QKVN + h * 192 + 64;
        const float* vsrc = ksrc + 64;
        #pragma unroll
        for (int it = 0; it < 4; it++) {
            int idx = it * 256 + tid;       // 1024 float4 = 64 rows x 16
            int r = idx >> 4, c4 = idx & 15;
            float4 kv = *(const float4*)(ksrc + (size_t)r * QKVN + c4 * 4);
            float* kd = Ks + r * AT_KP + c4 * 4;
            kd[0] = rna_tf32(kv.x); kd[1] = rna_tf32(kv.y);
            kd[2] = rna_tf32(kv.z); kd[3] = rna_tf32(kv.w);
            float4 vv = *(const float4*)(vsrc + (size_t)r * QKVN + c4 * 4);
            float* vd = Vs + r * AT_VP + c4 * 4;
            vd[0] = rna_tf32(vv.x); vd[1] = rna_tf32(vv.y);
            vd[2] = rna_tf32(vv.z); vd[3] = rna_tf32(vv.w);
        }
        if (tid < 64) mk[tid] = (mask[b * Ss + kt * 64 + tid] != 0) ? 1.f : 0.f;
        __syncthreads();

        // ---- scores: Q(16x64) . K^T, pair-k fragments ----
        float c[8][4];
        #pragma unroll
        for (int nt = 0; nt < 8; nt++)
            #pragma unroll
            for (int r = 0; r < 4; r++) c[nt][r] = 0.f;
        #pragma unroll
        for (int ks = 0; ks < 8; ks++) {
            const float* qp = Qs + (warpM + rq) * AT_QP + ks * 8 + 2 * qd;
            float2 q0 = *(const float2*)qp;
            float2 q1 = *(const float2*)(qp + 8 * AT_QP);
            uint32_t a[4];
            a[0] = __float_as_uint(q0.x);
            a[1] = __float_as_uint(q1.x);
            a[2] = __float_as_uint(q0.y);
            a[3] = __float_as_uint(q1.y);
            #pragma unroll
            for (int nt = 0; nt < 8; nt++) {
                float2 kk = *(const float2*)(Ks + (nt * 8 + rq) * AT_KP + ks * 8 + 2 * qd);
                uint32_t bfr[2];
                bfr[0] = __float_as_uint(kk.x);
                bfr[1] = __float_as_uint(kk.y);
                mma_tf32(c[nt], a, bfr);
            }
        }

        // ---- mask + online softmax ----
        float rmax0 = -1e30f, rmax1 = -1e30f;
        #pragma unroll
        for (int nt = 0; nt < 8; nt++) {
            int j0 = nt * 8 + 2 * qd;
            float mk0 = mk[j0], mk1 = mk[j0 + 1];
            if (mk0 != 0.f) { c[nt][0] = -1e9f; c[nt][2] = -1e9f; }
            if (mk1 != 0.f) { c[nt][1] = -1e9f; c[nt][3] = -1e9f; }
            rmax0 = fmaxf(rmax0, fmaxf(c[nt][0], c[nt][1]));
            rmax1 = fmaxf(rmax1, fmaxf(c[nt][2], c[nt][3]));
        }
        rmax0 = fmaxf(rmax0, __shfl_xor_sync(0xffffffffu, rmax0, 1));
        rmax0 = fmaxf(rmax0, __shfl_xor_sync(0xffffffffu, rmax0, 2));
        rmax1 = fmaxf(rmax1, __shfl_xor_sync(0xffffffffu, rmax1, 1));
        rmax1 = fmaxf(rmax1, __shfl_xor_sync(0xffffffffu, rmax1, 2));
        float mn0 = fmaxf(m0, rmax0), mn1 = fmaxf(m1, rmax1);
        float cor0 = __expf(m0 - mn0), cor1 = __expf(m1 - mn1);
        m0 = mn0; m1 = mn1;
        l0 *= cor0; l1 *= cor1;
        #pragma unroll
        for (int nt = 0; nt < 8; nt++) {
            oacc[nt][0] *= cor0; oacc[nt][1] *= cor0;
            oacc[nt][2] *= cor1; oacc[nt][3] *= cor1;
        }
        float ps0 = 0.f, ps1 = 0.f;
        #pragma unroll
        for (int nt = 0; nt < 8; nt++) {
            float p0 = __expf(c[nt][0] - m0);
            float p1 = __expf(c[nt][1] - m0);
            float p2 = __expf(c[nt][2] - m1);
            float p3 = __expf(c[nt][3] - m1);
            ps0 += p0 + p1; ps1 += p2 + p3;
            c[nt][0] = rna_tf32(p0); c[nt][1] = rna_tf32(p1);
            c[nt][2] = rna_tf32(p2); c[nt][3] = rna_tf32(p3);
        }
        l0 += ps0; l1 += ps1;

        // ---- store P (warp-private rows), then P.V with pair-k frags ----
        #pragma unroll
        for (int nt = 0; nt < 8; nt++) {
            float* pp = Ps + (warpM + rq) * AT_PP + nt * 8 + 2 * qd;
            float2 w1; w1.x = c[nt][0]; w1.y = c[nt][1];
            float2 w2; w2.x = c[nt][2]; w2.y = c[nt][3];
            *(float2*)pp = w1;
            *(float2*)(pp + 8 * AT_PP) = w2;
        }
        __syncwarp();
        #pragma unroll
        for (int ks = 0; ks < 8; ks++) {
            const float* pa = Ps + (warpM + rq) * AT_PP + ks * 8 + 2 * qd;
            float2 p0 = *(const float2*)pa;
            float2 p1 = *(const float2*)(pa + 8 * AT_PP);
            uint32_t a[4];
            a[0] = __float_as_uint(p0.x);
            a[1] = __float_as_uint(p1.x);
            a[2] = __float_as_uint(p0.y);
            a[3] = __float_as_uint(p1.y);
            #pragma unroll
            for (int nt = 0; nt < 8; nt++) {
                // V rows (natural j = ks*8 + 2qd, +1) to match pair-k order
                const float* vp = Vs + (ks * 8 + 2 * qd) * AT_VP + nt * 8 + rq;
                uint32_t bfr[2];
                bfr[0] = __float_as_uint(vp[0]);
                bfr[1] = __float_as_uint(vp[AT_VP]);
                mma_tf32(oacc[nt], a, bfr);
            }
        }
    }

    // final: row sums across quad, normalize, write (RNA for next GEMM A)
    l0 += __shfl_xor_sync(0xffffffffu, l0, 1);
    l0 += __shfl_xor_sync(0xffffffffu, l0, 2);
    l1 += __shfl_xor_sync(0xffffffffu, l1, 1);
    l1 += __shfl_xor_sync(0xffffffffu, l1, 2);
    float inv0 = 1.f / l0, inv1 = 1.f / l1;
    int row0 = base_q + warpM + rq;
    #pragma unroll
    for (int nt = 0; nt < 8; nt++) {
        int col = h * HDd + nt * 8 + 2 * qd;
        float2 w1; w1.x = rna_tf32(oacc[nt][0] * inv0); w1.y = rna_tf32(oacc[nt][1] * inv0);
        float2 w2; w2.x = rna_tf32(oacc[nt][2] * inv1); w2.y = rna_tf32(oacc[nt][3] * inv1);
        *(float2*)(att + (size_t)row0 * Dd + col)       = w1;
        *(float2*)(att + (size_t)(row0 + 8) * Dd + col) = w2;
    }
}

// ---------------- pooled LN + classifier ----------------
__global__ __launch_bounds__(256)
void pooled_kernel(const float* __restrict__ x,
                   const float* __restrict__ hs,
                   const float* __restrict__ hb,
                   const float* __restrict__ cw,
                   const float* __restrict__ cb,
                   float* __restrict__ out)
{
    __shared__ float buf[16];
    int b = blockIdx.x;
    int t = threadIdx.x;
    const float* xr = x + (size_t)b * Ss * Dd;
    float v0 = xr[t], v1 = xr[t + 256], v2 = xr[t + 512];
    float sum = v0 + v1 + v2;
    float sq  = v0*v0 + v1*v1 + v2*v2;
    blockReduce2(sum, sq, buf);
    float mean = sum * (1.0f / Dd);
    float var  = sq * (1.0f / Dd) - mean * mean;
    float rstd = rsqrtf(var + LN_EPS);
    float h0 = (v0 - mean) * rstd * hs[t]       + hb[t];
    float h1 = (v1 - mean) * rstd * hs[t + 256] + hb[t + 256];
    float h2 = (v2 - mean) * rstd * hs[t + 512] + hb[t + 512];
    float p0 = h0 * cw[t * 2]     + h1 * cw[(t + 256) * 2]     + h2 * cw[(t + 512) * 2];
    float p1 = h0 * cw[t * 2 + 1] + h1 * cw[(t + 256) * 2 + 1] + h2 * cw[(t + 512) * 2 + 1];
    blockReduce2(p0, p1, buf);
    if (t == 0) {
        out[b * Cc + 0] = p0 + cb[0];
        out[b * Cc + 1] = p1 + cb[1];
    }
}

// ---------------- launcher ----------------
extern "C" void kernel_launch(void* const* d_in, const int* in_sizes, int n_in,
                              void* d_out, int out_size)
{
    const int*   ids    = (const int*)  d_in[0];
    const int*   mask   = (const int*)  d_in[1];
    const float* tok    = (const float*)d_in[2];
    const float* pos    = (const float*)d_in[3];
    const float* qkv_w  = (const float*)d_in[4];
    const float* qkv_b  = (const float*)d_in[5];
    const float* out_w  = (const float*)d_in[6];
    const float* out_b  = (const float*)d_in[7];
    const float* n1_s   = (const float*)d_in[8];
    const float* n1_b   = (const float*)d_in[9];
    const float* ff1_w  = (const float*)d_in[10];
    const float* ff1_b  = (const float*)d_in[11];
    const float* ff2_w  = (const float*)d_in[12];
    const float* ff2_b  = (const float*)d_in[13];
    const float* n2_s   = (const float*)d_in[14];
    const float* n2_b   = (const float*)d_in[15];
    const float* hln_s  = (const float*)d_in[16];
    const float* hln_b  = (const float*)d_in[17];
    const float* cls_w  = (const float*)d_in[18];
    const float* cls_b  = (const float*)d_in[19];
    float* out = (float*)d_out;

    float *x, *h, *qkvb, *attb, *ffb, *wt;
    cudaGetSymbolAddress((void**)&x,    g_x);
    cudaGetSymbolAddress((void**)&h,    g_h);
    cudaGetSymbolAddress((void**)&qkvb, g_qkv);
    cudaGetSymbolAddress((void**)&attb, g_att);
    cudaGetSymbolAddress((void**)&ffb,  g_ff);
    cudaGetSymbolAddress((void**)&wt,   g_wt);

    cudaFuncSetAttribute(attn_mma_kernel, cudaFuncAttributeMaxDynamicSharedMemorySize, ATT_SMEM);
    cudaFuncSetAttribute(mma_gemm<768>,   cudaFuncAttributeMaxDynamicSharedMemorySize, GEMM_SMEM);
    cudaFuncSetAttribute(mma_gemm<3072>,  cudaFuncAttributeMaxDynamicSharedMemorySize, GEMM_SMEM);

    int embed_total = Mrows * (Dd / 4);
    embed_kernel<<<(embed_total + 255) / 256, 256>>>(ids, tok, pos, x);

    for (int i = 0; i < Ll; i++) {
        // LN1 -> h (tf32-rounded)
        ln_kernel<<<Mrows, 256>>>(x, n1_s + i * Dd, n1_b + i * Dd, h);

        // qkv: h[8192,768] @ W[768,2304]
        transpose_rna_kernel<<<dim3(QKVN / 32, Dd / 32), 256>>>(qkv_w + (size_t)i * Dd * QKVN, wt, Dd, QKVN);
        mma_gemm<768><<<dim3(QKVN / 256, Mrows / 128), 256, GEMM_SMEM>>>(
            h, wt, qkv_b + (size_t)i * QKVN, nullptr, qkvb, QKVN, 0, 0);

        attn_mma_kernel<<<dim3(Ss / 128, Hh, Bb), 256, ATT_SMEM>>>(qkvb, mask, attb);

        // out proj + residual: x = x + att @ W
        transpose_rna_kernel<<<dim3(Dd / 32, Dd / 32), 256>>>(out_w + (size_t)i * Dd * Dd, wt, Dd, Dd);
        mma_gemm<768><<<dim3(Dd / 256, Mrows / 128), 256, GEMM_SMEM>>>(
            attb, wt, out_b + (size_t)i * Dd, x, x, Dd, 0, 0);

        // LN2 -> h
        ln_kernel<<<Mrows, 256>>>(x, n2_s + i * Dd, n2_b + i * Dd, h);

        // ff1 + relu (output tf32-rounded: feeds ff2 as A)
        transpose_rna_kernel<<<dim3(DFf / 32, Dd / 32), 256>>>(ff1_w + (size_t)i * Dd * DFf, wt, Dd, DFf);
        mma_gemm<768><<<dim3(DFf / 256, Mrows / 128), 256, GEMM_SMEM>>>(
            h, wt, ff1_b + (size_t)i * DFf, nullptr, ffb, DFf, 1, 1);

        // ff2 + residual
        transpose_rna_kernel<<<dim3(Dd / 32, DFf / 32), 256>>>(ff2_w + (size_t)i * DFf * Dd, wt, DFf, Dd);
        mma_gemm<3072><<<dim3(Dd / 256, Mrows / 128), 256, GEMM_SMEM>>>(
            ffb, wt, ff2_b + (size_t)i * Dd, x, x, Dd, 0, 0);
    }

    pooled_kernel<<<Bb, 256>>>(x, hln_s, hln_b, cls_w, cls_b, out);
}

// round 7
// speedup vs baseline: 2.2588x; 2.2588x over previous
#include <cuda_runtime.h>
#include <cuda_fp16.h>
#include <cstdint>
#include <math.h>

#define Bb   8
#define Ss   1024
#define Dd   768
#define Hh   12
#define HDd  64
#define Ll   6
#define DFf  3072
#define Cc   2
#define Mrows (Bb*Ss)      /* 8192 */
#define QKVN  (3*Dd)       /* 2304 */
#define LN_EPS 1e-5f

// ---------------- scratch (device globals: allocation-free) ----------------
__device__ float  g_x[Mrows*Dd];
__device__ __half g_h[Mrows*Dd];
__device__ __half g_qkv[Mrows*QKVN];
__device__ __half g_att[Mrows*Dd];
__device__ __half g_ff[Mrows*DFf];
__device__ __half g_wt[DFf*Dd];     // transposed half weights (max 3072*768)

// ======================= helpers =======================
__device__ __forceinline__ uint32_t smem_to_u32(const void* p) {
    uint32_t a;
    asm("{ .reg .u64 t; cvta.to.shared.u64 t, %1; cvt.u32.u64 %0, t; }" : "=r"(a) : "l"(p));
    return a;
}
__device__ __forceinline__ float rna_tf32(float v) {
    asm("cvt.rna.tf32.f32 %0, %0;" : "+f"(v));
    return v;
}
#define CP_ASYNC16(dst, src) \
    asm volatile("cp.async.cg.shared.global [%0], [%1], 16;" :: "r"(dst), "l"(src) : "memory")
#define CP_COMMIT() asm volatile("cp.async.commit_group;" ::: "memory")
#define CP_WAIT0()  asm volatile("cp.async.wait_group 0;" ::: "memory")

// fp16 inputs, fp32 accumulate
__device__ __forceinline__ void mma_f16(float* d, const uint32_t* a, const uint32_t* b) {
    asm volatile(
        "mma.sync.aligned.m16n8k16.row.col.f32.f16.f16.f32 "
        "{%0,%1,%2,%3}, {%4,%5,%6,%7}, {%8,%9}, {%0,%1,%2,%3};"
        : "+f"(d[0]), "+f"(d[1]), "+f"(d[2]), "+f"(d[3])
        : "r"(a[0]), "r"(a[1]), "r"(a[2]), "r"(a[3]), "r"(b[0]), "r"(b[1]));
}
// tf32 (attention)
__device__ __forceinline__ void mma_tf32(float* d, const uint32_t* a, const uint32_t* b) {
    asm volatile(
        "mma.sync.aligned.m16n8k8.row.col.f32.tf32.tf32.f32 "
        "{%0,%1,%2,%3}, {%4,%5,%6,%7}, {%8,%9}, {%0,%1,%2,%3};"
        : "+f"(d[0]), "+f"(d[1]), "+f"(d[2]), "+f"(d[3])
        : "r"(a[0]), "r"(a[1]), "r"(a[2]), "r"(a[3]), "r"(b[0]), "r"(b[1]));
}

// ---------------- embed ----------------
__global__ void embed_kernel(const int* __restrict__ ids,
                             const float* __restrict__ tok,
                             const float* __restrict__ pos,
                             float* __restrict__ x)
{
    const float sc = 27.712812921102035f; // sqrt(768)
    int i = blockIdx.x * blockDim.x + threadIdx.x;
    int total = Mrows * (Dd / 4);
    if (i >= total) return;
    int row = i / (Dd / 4);
    int c4  = i - row * (Dd / 4);
    int s   = row & (Ss - 1);
    int id  = ids[row];
    const float4* t4 = (const float4*)tok;
    const float4* p4 = (const float4*)pos;
    float4 tv = t4[(size_t)id * (Dd/4) + c4];
    float4 pv = p4[(size_t)s  * (Dd/4) + c4];
    float4 o;
    o.x = (tv.x + pv.x) * sc;
    o.y = (tv.y + pv.y) * sc;
    o.z = (tv.z + pv.z) * sc;
    o.w = (tv.w + pv.w) * sc;
    ((float4*)x)[i] = o;
}

// ---------------- block reduce ----------------
__device__ __forceinline__ void blockReduce2(float& a, float& b, float* buf)
{
    #pragma unroll
    for (int o = 16; o; o >>= 1) {
        a += __shfl_xor_sync(0xffffffffu, a, o);
        b += __shfl_xor_sync(0xffffffffu, b, o);
    }
    int w = threadIdx.x >> 5;
    if ((threadIdx.x & 31) == 0) { buf[w] = a; buf[8 + w] = b; }
    __syncthreads();
    a = 0.f; b = 0.f;
    #pragma unroll
    for (int i = 0; i < 8; i++) { a += buf[i]; b += buf[8 + i]; }
    __syncthreads();
}

// ---------------- layernorm (half output: feeds GEMM A) ----------------
__global__ __launch_bounds__(256)
void ln_kernel(const float* __restrict__ x,
               const float* __restrict__ gs,
               const float* __restrict__ gb,
               __half* __restrict__ out)
{
    __shared__ float buf[16];
    int row = blockIdx.x;
    int t = threadIdx.x;
    const float* xr = x + (size_t)row * Dd;
    float v0 = xr[t], v1 = xr[t + 256], v2 = xr[t + 512];
    float sum = v0 + v1 + v2;
    float sq  = v0*v0 + v1*v1 + v2*v2;
    blockReduce2(sum, sq, buf);
    float mean = sum * (1.0f / Dd);
    float var  = sq * (1.0f / Dd) - mean * mean;
    float rstd = rsqrtf(var + LN_EPS);
    __half* orow = out + (size_t)row * Dd;
    orow[t]       = __float2half_rn((v0 - mean) * rstd * gs[t]       + gb[t]);
    orow[t + 256] = __float2half_rn((v1 - mean) * rstd * gs[t + 256] + gb[t + 256]);
    orow[t + 512] = __float2half_rn((v2 - mean) * rstd * gs[t + 512] + gb[t + 512]);
}

// ---------------- weight transpose to half: Wt[N,K] = h(W[K,N]^T) ----------
__global__ __launch_bounds__(256)
void transpose_h_kernel(const float* __restrict__ W, __half* __restrict__ Wt, int K, int N)
{
    __shared__ float t[32][33];
    int n0 = blockIdx.x * 32, k0 = blockIdx.y * 32;
    int x = threadIdx.x & 31, y = threadIdx.x >> 5; // 32x8
    #pragma unroll
    for (int i = 0; i < 32; i += 8)
        t[y + i][x] = W[(size_t)(k0 + y + i) * N + n0 + x];
    __syncthreads();
    #pragma unroll
    for (int i = 0; i < 32; i += 8)
        Wt[(size_t)(n0 + y + i) * K + k0 + x] = __float2half_rn(t[x][y + i]);
}

// ---------------- fp16 mma.sync GEMM ----------------
// C[M,N] = A[M,K] @ Bt[N,K]^T (+bias)(+res)(relu?), fp32 accumulate.
// BM=BN=128, BK=64 (halves), 256 threads, warp grid 2x4 (warp 64x32),
// 2-stage cp.async. Rows padded to 80 halves (160B: 16B-aligned, and
// stride 20 x 8B == 4 mod 16 -> all LDS.64 frag phases conflict-free).
// k-permutation: frag slots (2qd,2qd+1 | 2qd+8,2qd+9) carry natural
// k (4qd..4qd+3) for BOTH operands -> contiguous LDS.64 loads.
#define GPH 80                       /* halves per padded row */
#define ATILEH (128*GPH)             /* halves per tile */
#define STGH (2*ATILEH)              /* A+B halves per stage */
#define GEMM_SMEM (2*STGH*2)         /* 81920 bytes */

template<int K, int OUTH>
__global__ __launch_bounds__(256, 2)
void mma_gemm(const __half* __restrict__ A, const __half* __restrict__ Bt,
              const float* __restrict__ bias, const float* __restrict__ res,
              void* __restrict__ Cv, int N, int relu)
{
    extern __shared__ __half smh[];
    uint32_t sb = smem_to_u32(smh);
    int tid = threadIdx.x, lane = tid & 31, wid = tid >> 5;
    int rq = lane >> 2, qd = lane & 3;
    int warpM = (wid >> 2) * 64, warpN = (wid & 3) * 32;
    int m0 = blockIdx.y * 128, n0 = blockIdx.x * 128;
    const __half* Abase = A  + (size_t)m0 * K;
    const __half* Bbase = Bt + (size_t)n0 * K;
    constexpr int KI = K >> 6;

    float acc[4][4][4];
    #pragma unroll
    for (int mt = 0; mt < 4; mt++)
        #pragma unroll
        for (int nt = 0; nt < 4; nt++)
            #pragma unroll
            for (int r = 0; r < 4; r++) acc[mt][nt][r] = 0.f;

    // each stage: A tile 128x64 halves (8 x 16B chunks/row), B same.
    #define ISSUE_STAGE(I) do {                                                   \
        int _st = (I) & 1;                                                         \
        int _k0 = (I) << 6;                                                        \
        uint32_t _base = sb + (uint32_t)_st * (STGH * 2);                          \
        _Pragma("unroll")                                                          \
        for (int _it = 0; _it < 4; _it++) {                                        \
            int _idx = _it * 256 + tid;                                            \
            int _r = _idx >> 3, _c = _idx & 7;                                     \
            CP_ASYNC16(_base + _r * 160 + _c * 16,                                 \
                       Abase + (size_t)_r * K + _k0 + _c * 8);                     \
            CP_ASYNC16(_base + ATILEH * 2 + _r * 160 + _c * 16,                    \
                       Bbase + (size_t)_r * K + _k0 + _c * 8);                     \
        }                                                                          \
    } while (0)

    ISSUE_STAGE(0); CP_COMMIT();

    for (int i = 0; i < KI; i++) {
        CP_WAIT0();
        __syncthreads();
        if (i + 1 < KI) { ISSUE_STAGE(i + 1); CP_COMMIT(); }

        const __half* As = smh + (i & 1) * STGH;
        const __half* Bs = As + ATILEH;

        #pragma unroll
        for (int ks = 0; ks < 4; ks++) {
            uint32_t a[4][4];
            #pragma unroll
            for (int mt = 0; mt < 4; mt++) {
                const __half* p = As + (warpM + mt * 16 + rq) * GPH + ks * 16 + 4 * qd;
                uint2 lo = *(const uint2*)p;
                uint2 hi = *(const uint2*)(p + 8 * GPH);
                a[mt][0] = lo.x; a[mt][2] = lo.y;
                a[mt][1] = hi.x; a[mt][3] = hi.y;
            }
            uint32_t b[4][2];
            #pragma unroll
            for (int nt = 0; nt < 4; nt++) {
                const __half* pb = Bs + (warpN + nt * 8 + rq) * GPH + ks * 16 + 4 * qd;
                uint2 v = *(const uint2*)pb;
                b[nt][0] = v.x; b[nt][1] = v.y;
            }
            #pragma unroll
            for (int mt = 0; mt < 4; mt++)
                #pragma unroll
                for (int nt = 0; nt < 4; nt++)
                    mma_f16(acc[mt][nt], a[mt], b[nt]);
        }
    }

    // epilogue
    #pragma unroll
    for (int mt = 0; mt < 4; mt++) {
        int r0 = m0 + warpM + mt * 16 + rq;
        #pragma unroll
        for (int nt = 0; nt < 4; nt++) {
            int c0 = n0 + warpN + nt * 8 + qd * 2;
            float2 bv = *(const float2*)(bias + c0);
            float v0 = acc[mt][nt][0] + bv.x;
            float v1 = acc[mt][nt][1] + bv.y;
            float v2 = acc[mt][nt][2] + bv.x;
            float v3 = acc[mt][nt][3] + bv.y;
            if (res) {
                float2 q1 = *(const float2*)(res + (size_t)r0 * N + c0);
                float2 q2 = *(const float2*)(res + (size_t)(r0 + 8) * N + c0);
                v0 += q1.x; v1 += q1.y; v2 += q2.x; v3 += q2.y;
            }
            if (relu) {
                v0 = fmaxf(v0, 0.f); v1 = fmaxf(v1, 0.f);
                v2 = fmaxf(v2, 0.f); v3 = fmaxf(v3, 0.f);
            }
            if (OUTH) {
                __half* C = (__half*)Cv;
                *(__half2*)(C + (size_t)r0 * N + c0)       = __floats2half2_rn(v0, v1);
                *(__half2*)(C + (size_t)(r0 + 8) * N + c0) = __floats2half2_rn(v2, v3);
            } else {
                float* C = (float*)Cv;
                float2 o1; o1.x = v0; o1.y = v1;
                float2 o2; o2.x = v2; o2.y = v3;
                *(float2*)(C + (size_t)r0 * N + c0)       = o1;
                *(float2*)(C + (size_t)(r0 + 8) * N + c0) = o2;
            }
        }
    }
}

// ---------------- tensor-core flash attention (tf32, half I/O) -------------
// grid (S/128, H, B), 256 threads = 8 warps, warp w owns q-rows [16w,16w+16).
// Inputs are half (exact in tf32); P gets rna before P.V.
#define AT_QP 72
#define AT_KP 72
#define AT_VP 68
#define AT_PP 72
#define ATT_SMEM ((128*AT_QP + 64*AT_KP + 64*AT_VP + 128*AT_PP + 64) * 4)

__global__ __launch_bounds__(256, 2)
void attn_mma_kernel(const __half* __restrict__ qkv,
                     const int* __restrict__ mask,
                     __half* __restrict__ att)
{
    extern __shared__ float sa[];
    float* Qs = sa;                    // [128][72]
    float* Ks = Qs + 128 * AT_QP;      // [64][72]
    float* Vs = Ks + 64 * AT_KP;       // [64][68]
    float* Ps = Vs + 64 * AT_VP;       // [128][72]
    float* mk = Ps + 128 * AT_PP;      // [64]

    int qb = blockIdx.x, h = blockIdx.y, b = blockIdx.z;
    int tid = threadIdx.x, lane = tid & 31, wid = tid >> 5;
    int rq = lane >> 2, qd = lane & 3;
    int warpM = wid * 16;
    int base_q = b * Ss + qb * 128;

    // load Q tile (half -> float, scale 1/8 exact)
    const __half* qsrc = qkv + (size_t)base_q * QKVN + h * 192;
    #pragma unroll
    for (int it = 0; it < 4; it++) {
        int idx = it * 256 + tid;           // 1024 chunks = 128 rows x 8
        int r = idx >> 3, c8 = idx & 7;
        uint4 raw = *(const uint4*)(qsrc + (size_t)r * QKVN + c8 * 8);
        const __half2* hp = (const __half2*)&raw;
        float* dst = Qs + r * AT_QP + c8 * 8;
        #pragma unroll
        for (int j = 0; j < 4; j++) {
            float2 f = __half22float2(hp[j]);
            dst[j * 2 + 0] = f.x * 0.125f;
            dst[j * 2 + 1] = f.y * 0.125f;
        }
    }

    float oacc[8][4];
    #pragma unroll
    for (int nt = 0; nt < 8; nt++)
        #pragma unroll
        for (int r = 0; r < 4; r++) oacc[nt][r] = 0.f;
    float m0 = -1e30f, m1 = -1e30f, l0 = 0.f, l1 = 0.f;

    __syncthreads();   // Q ready

    for (int kt = 0; kt < Ss / 64; kt++) {
        if (kt) __syncthreads();   // previous PV reads of Vs done
        const __half* ksrc = qkv + (size_t)(b * Ss + kt * 64) * QKVN + h * 192 + 64;
        const __half* vsrc = ksrc + 64;
        #pragma unroll
        for (int it = 0; it < 2; it++) {
            int idx = it * 256 + tid;       // 512 chunks = 64 rows x 8
            int r = idx >> 3, c8 = idx & 7;
            uint4 kraw = *(const uint4*)(ksrc + (size_t)r * QKVN + c8 * 8);
            uint4 vraw = *(const uint4*)(vsrc + (size_t)r * QKVN + c8 * 8);
            const __half2* kp = (const __half2*)&kraw;
            const __half2* vp = (const __half2*)&vraw;
            float* kd = Ks + r * AT_KP + c8 * 8;
            float* vd = Vs + r * AT_VP + c8 * 8;
            #pragma unroll
            for (int j = 0; j < 4; j++) {
                float2 kf = __half22float2(kp[j]);
                float2 vf = __half22float2(vp[j]);
                kd[j * 2 + 0] = kf.x; kd[j * 2 + 1] = kf.y;
                vd[j * 2 + 0] = vf.x; vd[j * 2 + 1] = vf.y;
            }
        }
        if (tid < 64) mk[tid] = (mask[b * Ss + kt * 64 + tid] != 0) ? 1.f : 0.f;
        __syncthreads();

        // ---- scores: Q(16x64) . K^T, pair-k fragments ----
        float c[8][4];
        #pragma unroll
        for (int nt = 0; nt < 8; nt++)
            #pragma unroll
            for (int r = 0; r < 4; r++) c[nt][r] = 0.f;
        #pragma unroll
        for (int ks = 0; ks < 8; ks++) {
            const float* qp = Qs + (warpM + rq) * AT_QP + ks * 8 + 2 * qd;
            float2 q0 = *(const float2*)qp;
            float2 q1 = *(const float2*)(qp + 8 * AT_QP);
            uint32_t a[4];
            a[0] = __float_as_uint(q0.x);
            a[1] = __float_as_uint(q1.x);
            a[2] = __float_as_uint(q0.y);
            a[3] = __float_as_uint(q1.y);
            #pragma unroll
            for (int nt = 0; nt < 8; nt++) {
                float2 kk = *(const float2*)(Ks + (nt * 8 + rq) * AT_KP + ks * 8 + 2 * qd);
                uint32_t bfr[2];
                bfr[0] = __float_as_uint(kk.x);
                bfr[1] = __float_as_uint(kk.y);
                mma_tf32(c[nt], a, bfr);
            }
        }

        // ---- mask + online softmax ----
        float rmax0 = -1e30f, rmax1 = -1e30f;
        #pragma unroll
        for (int nt = 0; nt < 8; nt++) {
            int j0 = nt * 8 + 2 * qd;
            float mk0 = mk[j0], mk1 = mk[j0 + 1];
            if (mk0 != 0.f) { c[nt][0] = -1e9f; c[nt][2] = -1e9f; }
            if (mk1 != 0.f) { c[nt][1] = -1e9f; c[nt][3] = -1e9f; }
            rmax0 = fmaxf(rmax0, fmaxf(c[nt][0], c[nt][1]));
            rmax1 = fmaxf(rmax1, fmaxf(c[nt][2], c[nt][3]));
        }
        rmax0 = fmaxf(rmax0, __shfl_xor_sync(0xffffffffu, rmax0, 1));
        rmax0 = fmaxf(rmax0, __shfl_xor_sync(0xffffffffu, rmax0, 2));
        rmax1 = fmaxf(rmax1, __shfl_xor_sync(0xffffffffu, rmax1, 1));
        rmax1 = fmaxf(rmax1, __shfl_xor_sync(0xffffffffu, rmax1, 2));
        float mn0 = fmaxf(m0, rmax0), mn1 = fmaxf(m1, rmax1);
        float cor0 = __expf(m0 - mn0), cor1 = __expf(m1 - mn1);
        m0 = mn0; m1 = mn1;
        l0 *= cor0; l1 *= cor1;
        #pragma unroll
        for (int nt = 0; nt < 8; nt++) {
            oacc[nt][0] *= cor0; oacc[nt][1] *= cor0;
            oacc[nt][2] *= cor1; oacc[nt][3] *= cor1;
        }
        float ps0 = 0.f, ps1 = 0.f;
        #pragma unroll
        for (int nt = 0; nt < 8; nt++) {
            float p0 = __expf(c[nt][0] - m0);
            float p1 = __expf(c[nt][1] - m0);
            float p2 = __expf(c[nt][2] - m1);
            float p3 = __expf(c[nt][3] - m1);
            ps0 += p0 + p1; ps1 += p2 + p3;
            c[nt][0] = rna_tf32(p0); c[nt][1] = rna_tf32(p1);
            c[nt][2] = rna_tf32(p2); c[nt][3] = rna_tf32(p3);
        }
        l0 += ps0; l1 += ps1;

        // ---- store P (warp-private rows), then P.V with pair-k frags ----
        #pragma unroll
        for (int nt = 0; nt < 8; nt++) {
            float* pp = Ps + (warpM + rq) * AT_PP + nt * 8 + 2 * qd;
            float2 w1; w1.x = c[nt][0]; w1.y = c[nt][1];
            float2 w2; w2.x = c[nt][2]; w2.y = c[nt][3];
            *(float2*)pp = w1;
            *(float2*)(pp + 8 * AT_PP) = w2;
        }
        __syncwarp();
        #pragma unroll
        for (int ks = 0; ks < 8; ks++) {
            const float* pa = Ps + (warpM + rq) * AT_PP + ks * 8 + 2 * qd;
            float2 p0 = *(const float2*)pa;
            float2 p1 = *(const float2*)(pa + 8 * AT_PP);
            uint32_t a[4];
            a[0] = __float_as_uint(p0.x);
            a[1] = __float_as_uint(p1.x);
            a[2] = __float_as_uint(p0.y);
            a[3] = __float_as_uint(p1.y);
            #pragma unroll
            for (int nt = 0; nt < 8; nt++) {
                const float* vp = Vs + (ks * 8 + 2 * qd) * AT_VP + nt * 8 + rq;
                uint32_t bfr[2];
                bfr[0] = __float_as_uint(vp[0]);
                bfr[1] = __float_as_uint(vp[AT_VP]);
                mma_tf32(oacc[nt], a, bfr);
            }
        }
    }

    // final: row sums across quad, normalize, write half (next GEMM A)
    l0 += __shfl_xor_sync(0xffffffffu, l0, 1);
    l0 += __shfl_xor_sync(0xffffffffu, l0, 2);
    l1 += __shfl_xor_sync(0xffffffffu, l1, 1);
    l1 += __shfl_xor_sync(0xffffffffu, l1, 2);
    float inv0 = 1.f / l0, inv1 = 1.f / l1;
    int row0 = base_q + warpM + rq;
    #pragma unroll
    for (int nt = 0; nt < 8; nt++) {
        int col = h * HDd + nt * 8 + 2 * qd;
        *(__half2*)(att + (size_t)row0 * Dd + col) =
            __floats2half2_rn(oacc[nt][0] * inv0, oacc[nt][1] * inv0);
        *(__half2*)(att + (size_t)(row0 + 8) * Dd + col) =
            __floats2half2_rn(oacc[nt][2] * inv1, oacc[nt][3] * inv1);
    }
}

// ---------------- pooled LN + classifier ----------------
__global__ __launch_bounds__(256)
void pooled_kernel(const float* __restrict__ x,
                   const float* __restrict__ hs,
                   const float* __restrict__ hb,
                   const float* __restrict__ cw,
                   const float* __restrict__ cb,
                   float* __restrict__ out)
{
    __shared__ float buf[16];
    int b = blockIdx.x;
    int t = threadIdx.x;
    const float* xr = x + (size_t)b * Ss * Dd;
    float v0 = xr[t], v1 = xr[t + 256], v2 = xr[t + 512];
    float sum = v0 + v1 + v2;
    float sq  = v0*v0 + v1*v1 + v2*v2;
    blockReduce2(sum, sq, buf);
    float mean = sum * (1.0f / Dd);
    float var  = sq * (1.0f / Dd) - mean * mean;
    float rstd = rsqrtf(var + LN_EPS);
    float h0 = (v0 - mean) * rstd * hs[t]       + hb[t];
    float h1 = (v1 - mean) * rstd * hs[t + 256] + hb[t + 256];
    float h2 = (v2 - mean) * rstd * hs[t + 512] + hb[t + 512];
    float p0 = h0 * cw[t * 2]     + h1 * cw[(t + 256) * 2]     + h2 * cw[(t + 512) * 2];
    float p1 = h0 * cw[t * 2 + 1] + h1 * cw[(t + 256) * 2 + 1] + h2 * cw[(t + 512) * 2 + 1];
    blockReduce2(p0, p1, buf);
    if (t == 0) {
        out[b * Cc + 0] = p0 + cb[0];
        out[b * Cc + 1] = p1 + cb[1];
    }
}

// ---------------- launcher ----------------
extern "C" void kernel_launch(void* const* d_in, const int* in_sizes, int n_in,
                              void* d_out, int out_size)
{
    const int*   ids    = (const int*)  d_in[0];
    const int*   mask   = (const int*)  d_in[1];
    const float* tok    = (const float*)d_in[2];
    const float* pos    = (const float*)d_in[3];
    const float* qkv_w  = (const float*)d_in[4];
    const float* qkv_b  = (const float*)d_in[5];
    const float* out_w  = (const float*)d_in[6];
    const float* out_b  = (const float*)d_in[7];
    const float* n1_s   = (const float*)d_in[8];
    const float* n1_b   = (const float*)d_in[9];
    const float* ff1_w  = (const float*)d_in[10];
    const float* ff1_b  = (const float*)d_in[11];
    const float* ff2_w  = (const float*)d_in[12];
    const float* ff2_b  = (const float*)d_in[13];
    const float* n2_s   = (const float*)d_in[14];
    const float* n2_b   = (const float*)d_in[15];
    const float* hln_s  = (const float*)d_in[16];
    const float* hln_b  = (const float*)d_in[17];
    const float* cls_w  = (const float*)d_in[18];
    const float* cls_b  = (const float*)d_in[19];
    float* out = (float*)d_out;

    float *x;
    __half *h, *qkvb, *attb, *ffb, *wt;
    cudaGetSymbolAddress((void**)&x,    g_x);
    cudaGetSymbolAddress((void**)&h,    g_h);
    cudaGetSymbolAddress((void**)&qkvb, g_qkv);
    cudaGetSymbolAddress((void**)&attb, g_att);
    cudaGetSymbolAddress((void**)&ffb,  g_ff);
    cudaGetSymbolAddress((void**)&wt,   g_wt);

    cudaFuncSetAttribute(attn_mma_kernel,  cudaFuncAttributeMaxDynamicSharedMemorySize, ATT_SMEM);
    cudaFuncSetAttribute(mma_gemm<768,1>,  cudaFuncAttributeMaxDynamicSharedMemorySize, GEMM_SMEM);
    cudaFuncSetAttribute(mma_gemm<768,0>,  cudaFuncAttributeMaxDynamicSharedMemorySize, GEMM_SMEM);
    cudaFuncSetAttribute(mma_gemm<3072,0>, cudaFuncAttributeMaxDynamicSharedMemorySize, GEMM_SMEM);

    int embed_total = Mrows * (Dd / 4);
    embed_kernel<<<(embed_total + 255) / 256, 256>>>(ids, tok, pos, x);

    for (int i = 0; i < Ll; i++) {
        // LN1 -> h (half)
        ln_kernel<<<Mrows, 256>>>(x, n1_s + i * Dd, n1_b + i * Dd, h);

        // qkv: h[8192,768] @ W[768,2304] -> half qkv
        transpose_h_kernel<<<dim3(QKVN / 32, Dd / 32), 256>>>(qkv_w + (size_t)i * Dd * QKVN, wt, Dd, QKVN);
        mma_gemm<768,1><<<dim3(QKVN / 128, Mrows / 128), 256, GEMM_SMEM>>>(
            h, wt, qkv_b + (size_t)i * QKVN, nullptr, qkvb, QKVN, 0);

        attn_mma_kernel<<<dim3(Ss / 128, Hh, Bb), 256, ATT_SMEM>>>(qkvb, mask, attb);

        // out proj + residual: x = x + att @ W (float out)
        transpose_h_kernel<<<dim3(Dd / 32, Dd / 32), 256>>>(out_w + (size_t)i * Dd * Dd, wt, Dd, Dd);
        mma_gemm<768,0><<<dim3(Dd / 128, Mrows / 128), 256, GEMM_SMEM>>>(
            attb, wt, out_b + (size_t)i * Dd, x, x, Dd, 0);

        // LN2 -> h
        ln_kernel<<<Mrows, 256>>>(x, n2_s + i * Dd, n2_b + i * Dd, h);

        // ff1 + relu -> half ffb
        transpose_h_kernel<<<dim3(DFf / 32, Dd / 32), 256>>>(ff1_w + (size_t)i * Dd * DFf, wt, Dd, DFf);
        mma_gemm<768,1><<<dim3(DFf / 128, Mrows / 128), 256, GEMM_SMEM>>>(
            h, wt, ff1_b + (size_t)i * DFf, nullptr, ffb, DFf, 1);

        // ff2 + residual (float out)
        transpose_h_kernel<<<dim3(Dd / 32, DFf / 32), 256>>>(ff2_w + (size_t)i * DFf * Dd, wt, DFf, Dd);
        mma_gemm<3072,0><<<dim3(Dd / 128, Mrows / 128), 256, GEMM_SMEM>>>(
            ffb, wt, ff2_b + (size_t)i * Dd, x, x, Dd, 0);
    }

    pooled_kernel<<<Bb, 256>>>(x, hln_s, hln_b, cls_w, cls_b, out);
}

// round 8
// speedup vs baseline: 2.7127x; 1.2009x over previous
#include <cuda_runtime.h>
#include <cuda_fp16.h>
#include <cstdint>
#include <math.h>

#define Bb   8
#define Ss   1024
#define Dd   768
#define Hh   12
#define HDd  64
#define Ll   6
#define DFf  3072
#define Cc   2
#define Mrows (Bb*Ss)      /* 8192 */
#define QKVN  (3*Dd)       /* 2304 */
#define LN_EPS 1e-5f

// ---------------- scratch (device globals: allocation-free) ----------------
__device__ float  g_x[Mrows*Dd];
__device__ __half g_h[Mrows*Dd];
__device__ __half g_qkv[Mrows*QKVN];
__device__ __half g_att[Mrows*Dd];
__device__ __half g_ff[Mrows*DFf];
__device__ __half g_wt[DFf*Dd];     // transposed half weights (max 3072*768)

// ======================= helpers =======================
__device__ __forceinline__ uint32_t smem_to_u32(const void* p) {
    uint32_t a;
    asm("{ .reg .u64 t; cvta.to.shared.u64 t, %1; cvt.u32.u64 %0, t; }" : "=r"(a) : "l"(p));
    return a;
}
#define CP_ASYNC16(dst, src) \
    asm volatile("cp.async.cg.shared.global [%0], [%1], 16;" :: "r"(dst), "l"(src) : "memory")
#define CP_COMMIT() asm volatile("cp.async.commit_group;" ::: "memory")
#define CP_WAIT0()  asm volatile("cp.async.wait_group 0;" ::: "memory")

// fp16 inputs, fp32 accumulate
__device__ __forceinline__ void mma_f16(float* d, const uint32_t* a, const uint32_t* b) {
    asm volatile(
        "mma.sync.aligned.m16n8k16.row.col.f32.f16.f16.f32 "
        "{%0,%1,%2,%3}, {%4,%5,%6,%7}, {%8,%9}, {%0,%1,%2,%3};"
        : "+f"(d[0]), "+f"(d[1]), "+f"(d[2]), "+f"(d[3])
        : "r"(a[0]), "r"(a[1]), "r"(a[2]), "r"(a[3]), "r"(b[0]), "r"(b[1]));
}
// ldmatrix x4 transposed (b16)
#define LDSM_X4_TRANS(r0, r1, r2, r3, addr) \
    asm volatile("ldmatrix.sync.aligned.m8n8.x4.trans.shared.b16 {%0,%1,%2,%3}, [%4];" \
        : "=r"(r0), "=r"(r1), "=r"(r2), "=r"(r3) : "r"(addr))

// ---------------- embed ----------------
__global__ void embed_kernel(const int* __restrict__ ids,
                             const float* __restrict__ tok,
                             const float* __restrict__ pos,
                             float* __restrict__ x)
{
    const float sc = 27.712812921102035f; // sqrt(768)
    int i = blockIdx.x * blockDim.x + threadIdx.x;
    int total = Mrows * (Dd / 4);
    if (i >= total) return;
    int row = i / (Dd / 4);
    int c4  = i - row * (Dd / 4);
    int s   = row & (Ss - 1);
    int id  = ids[row];
    const float4* t4 = (const float4*)tok;
    const float4* p4 = (const float4*)pos;
    float4 tv = t4[(size_t)id * (Dd/4) + c4];
    float4 pv = p4[(size_t)s  * (Dd/4) + c4];
    float4 o;
    o.x = (tv.x + pv.x) * sc;
    o.y = (tv.y + pv.y) * sc;
    o.z = (tv.z + pv.z) * sc;
    o.w = (tv.w + pv.w) * sc;
    ((float4*)x)[i] = o;
}

// ---------------- block reduce ----------------
__device__ __forceinline__ void blockReduce2(float& a, float& b, float* buf)
{
    #pragma unroll
    for (int o = 16; o; o >>= 1) {
        a += __shfl_xor_sync(0xffffffffu, a, o);
        b += __shfl_xor_sync(0xffffffffu, b, o);
    }
    int w = threadIdx.x >> 5;
    if ((threadIdx.x & 31) == 0) { buf[w] = a; buf[8 + w] = b; }
    __syncthreads();
    a = 0.f; b = 0.f;
    #pragma unroll
    for (int i = 0; i < 8; i++) { a += buf[i]; b += buf[8 + i]; }
    __syncthreads();
}

// ---------------- layernorm (half output: feeds GEMM A) ----------------
__global__ __launch_bounds__(256)
void ln_kernel(const float* __restrict__ x,
               const float* __restrict__ gs,
               const float* __restrict__ gb,
               __half* __restrict__ out)
{
    __shared__ float buf[16];
    int row = blockIdx.x;
    int t = threadIdx.x;
    const float* xr = x + (size_t)row * Dd;
    float v0 = xr[t], v1 = xr[t + 256], v2 = xr[t + 512];
    float sum = v0 + v1 + v2;
    float sq  = v0*v0 + v1*v1 + v2*v2;
    blockReduce2(sum, sq, buf);
    float mean = sum * (1.0f / Dd);
    float var  = sq * (1.0f / Dd) - mean * mean;
    float rstd = rsqrtf(var + LN_EPS);
    __half* orow = out + (size_t)row * Dd;
    orow[t]       = __float2half_rn((v0 - mean) * rstd * gs[t]       + gb[t]);
    orow[t + 256] = __float2half_rn((v1 - mean) * rstd * gs[t + 256] + gb[t + 256]);
    orow[t + 512] = __float2half_rn((v2 - mean) * rstd * gs[t + 512] + gb[t + 512]);
}

// ---------------- weight transpose to half: Wt[N,K] = h(W[K,N]^T) ----------
__global__ __launch_bounds__(256)
void transpose_h_kernel(const float* __restrict__ W, __half* __restrict__ Wt, int K, int N)
{
    __shared__ float t[32][33];
    int n0 = blockIdx.x * 32, k0 = blockIdx.y * 32;
    int x = threadIdx.x & 31, y = threadIdx.x >> 5; // 32x8
    #pragma unroll
    for (int i = 0; i < 32; i += 8)
        t[y + i][x] = W[(size_t)(k0 + y + i) * N + n0 + x];
    __syncthreads();
    #pragma unroll
    for (int i = 0; i < 32; i += 8)
        Wt[(size_t)(n0 + y + i) * K + k0 + x] = __float2half_rn(t[x][y + i]);
}

// ---------------- fp16 mma.sync GEMM ----------------
// C[M,N] = A[M,K] @ Bt[N,K]^T (+bias)(+res)(relu?), fp32 accumulate.
// BM=BN=128, BK=64 (halves), 256 threads, warp grid 2x4 (warp 64x32),
// 2-stage cp.async. Rows padded to 80 halves (160B, conflict-free LDS.64).
#define GPH 80                       /* halves per padded row */
#define ATILEH (128*GPH)             /* halves per tile */
#define STGH (2*ATILEH)              /* A+B halves per stage */
#define GEMM_SMEM (2*STGH*2)         /* 81920 bytes */

template<int K, int OUTH>
__global__ __launch_bounds__(256, 2)
void mma_gemm(const __half* __restrict__ A, const __half* __restrict__ Bt,
              const float* __restrict__ bias, const float* __restrict__ res,
              void* __restrict__ Cv, int N, int relu)
{
    extern __shared__ __half smh[];
    uint32_t sb = smem_to_u32(smh);
    int tid = threadIdx.x, lane = tid & 31, wid = tid >> 5;
    int rq = lane >> 2, qd = lane & 3;
    int warpM = (wid >> 2) * 64, warpN = (wid & 3) * 32;
    int m0 = blockIdx.y * 128, n0 = blockIdx.x * 128;
    const __half* Abase = A  + (size_t)m0 * K;
    const __half* Bbase = Bt + (size_t)n0 * K;
    constexpr int KI = K >> 6;

    float acc[4][4][4];
    #pragma unroll
    for (int mt = 0; mt < 4; mt++)
        #pragma unroll
        for (int nt = 0; nt < 4; nt++)
            #pragma unroll
            for (int r = 0; r < 4; r++) acc[mt][nt][r] = 0.f;

    #define ISSUE_STAGE(I) do {                                                   \
        int _st = (I) & 1;                                                         \
        int _k0 = (I) << 6;                                                        \
        uint32_t _base = sb + (uint32_t)_st * (STGH * 2);                          \
        _Pragma("unroll")                                                          \
        for (int _it = 0; _it < 4; _it++) {                                        \
            int _idx = _it * 256 + tid;                                            \
            int _r = _idx >> 3, _c = _idx & 7;                                     \
            CP_ASYNC16(_base + _r * 160 + _c * 16,                                 \
                       Abase + (size_t)_r * K + _k0 + _c * 8);                     \
            CP_ASYNC16(_base + ATILEH * 2 + _r * 160 + _c * 16,                    \
                       Bbase + (size_t)_r * K + _k0 + _c * 8);                     \
        }                                                                          \
    } while (0)

    ISSUE_STAGE(0); CP_COMMIT();

    for (int i = 0; i < KI; i++) {
        CP_WAIT0();
        __syncthreads();
        if (i + 1 < KI) { ISSUE_STAGE(i + 1); CP_COMMIT(); }

        const __half* As = smh + (i & 1) * STGH;
        const __half* Bs = As + ATILEH;

        #pragma unroll
        for (int ks = 0; ks < 4; ks++) {
            uint32_t a[4][4];
            #pragma unroll
            for (int mt = 0; mt < 4; mt++) {
                const __half* p = As + (warpM + mt * 16 + rq) * GPH + ks * 16 + 4 * qd;
                uint2 lo = *(const uint2*)p;
                uint2 hi = *(const uint2*)(p + 8 * GPH);
                a[mt][0] = lo.x; a[mt][2] = lo.y;
                a[mt][1] = hi.x; a[mt][3] = hi.y;
            }
            uint32_t b[4][2];
            #pragma unroll
            for (int nt = 0; nt < 4; nt++) {
                const __half* pb = Bs + (warpN + nt * 8 + rq) * GPH + ks * 16 + 4 * qd;
                uint2 v = *(const uint2*)pb;
                b[nt][0] = v.x; b[nt][1] = v.y;
            }
            #pragma unroll
            for (int mt = 0; mt < 4; mt++)
                #pragma unroll
                for (int nt = 0; nt < 4; nt++)
                    mma_f16(acc[mt][nt], a[mt], b[nt]);
        }
    }

    // epilogue
    #pragma unroll
    for (int mt = 0; mt < 4; mt++) {
        int r0 = m0 + warpM + mt * 16 + rq;
        #pragma unroll
        for (int nt = 0; nt < 4; nt++) {
            int c0 = n0 + warpN + nt * 8 + qd * 2;
            float2 bv = *(const float2*)(bias + c0);
            float v0 = acc[mt][nt][0] + bv.x;
            float v1 = acc[mt][nt][1] + bv.y;
            float v2 = acc[mt][nt][2] + bv.x;
            float v3 = acc[mt][nt][3] + bv.y;
            if (res) {
                float2 q1 = *(const float2*)(res + (size_t)r0 * N + c0);
                float2 q2 = *(const float2*)(res + (size_t)(r0 + 8) * N + c0);
                v0 += q1.x; v1 += q1.y; v2 += q2.x; v3 += q2.y;
            }
            if (relu) {
                v0 = fmaxf(v0, 0.f); v1 = fmaxf(v1, 0.f);
                v2 = fmaxf(v2, 0.f); v3 = fmaxf(v3, 0.f);
            }
            if (OUTH) {
                __half* C = (__half*)Cv;
                *(__half2*)(C + (size_t)r0 * N + c0)       = __floats2half2_rn(v0, v1);
                *(__half2*)(C + (size_t)(r0 + 8) * N + c0) = __floats2half2_rn(v2, v3);
            } else {
                float* C = (float*)Cv;
                float2 o1; o1.x = v0; o1.y = v1;
                float2 o2; o2.x = v2; o2.y = v3;
                *(float2*)(C + (size_t)r0 * N + c0)       = o1;
                *(float2*)(C + (size_t)(r0 + 8) * N + c0) = o2;
            }
        }
    }
}

// ---------------- fp16 tensor-core flash attention ----------------
// grid (S/128, H, B), 256 threads = 8 warps, warp w owns q-rows [16w,16w+16).
// QK^T: perm-k uint2 fragments (Qs/Ks pad 80h).
// P.V: natural-k (Ps pad 72h, half2 loads) + ldmatrix.x4.trans on V (pad 72h).
#define AQ 80
#define AK 80
#define AV 72
#define AP 72
#define ATT_SMEM ((128*AQ + 64*AK + 64*AV + 128*AP) * 2 + 64 * 4)

__global__ __launch_bounds__(256, 2)
void attn_mma_kernel(const __half* __restrict__ qkv,
                     const int* __restrict__ mask,
                     __half* __restrict__ att)
{
    extern __shared__ __half smha[];
    __half* Qs = smha;                 // [128][80]
    __half* Ks = Qs + 128 * AQ;        // [64][80]
    __half* Vs = Ks + 64 * AK;         // [64][72] natural [kvrow][dim]
    __half* Ps = Vs + 64 * AV;         // [128][72]
    float*  mk = (float*)(Ps + 128 * AP);  // [64]
    uint32_t vsb = smem_to_u32(Vs);

    int qb = blockIdx.x, h = blockIdx.y, b = blockIdx.z;
    int tid = threadIdx.x, lane = tid & 31, wid = tid >> 5;
    int rq = lane >> 2, qd = lane & 3;
    int warpM = wid * 16;
    int base_q = b * Ss + qb * 128;

    // load Q tile (scale 1/8, exact in fp16)
    const __half2 qscale = __float2half2_rn(0.125f);
    const __half* qsrc = qkv + (size_t)base_q * QKVN + h * 192;
    #pragma unroll
    for (int it = 0; it < 4; it++) {
        int idx = it * 256 + tid;           // 1024 chunks = 128 rows x 8
        int r = idx >> 3, c8 = idx & 7;
        uint4 raw = *(const uint4*)(qsrc + (size_t)r * QKVN + c8 * 8);
        __half2* hp = (__half2*)&raw;
        hp[0] = __hmul2(hp[0], qscale);
        hp[1] = __hmul2(hp[1], qscale);
        hp[2] = __hmul2(hp[2], qscale);
        hp[3] = __hmul2(hp[3], qscale);
        *(uint4*)(Qs + r * AQ + c8 * 8) = raw;
    }

    float oacc[8][4];
    #pragma unroll
    for (int nt = 0; nt < 8; nt++)
        #pragma unroll
        for (int r = 0; r < 4; r++) oacc[nt][r] = 0.f;
    float m0 = -1e30f, m1 = -1e30f, l0 = 0.f, l1 = 0.f;

    __syncthreads();   // Q ready

    for (int kt = 0; kt < Ss / 64; kt++) {
        if (kt) __syncthreads();   // previous PV reads of Vs done
        const __half* ksrc = qkv + (size_t)(b * Ss + kt * 64) * QKVN + h * 192 + 64;
        const __half* vsrc = ksrc + 64;
        #pragma unroll
        for (int it = 0; it < 2; it++) {
            int idx = it * 256 + tid;       // 512 chunks = 64 rows x 8
            int r = idx >> 3, c8 = idx & 7;
            uint4 kraw = *(const uint4*)(ksrc + (size_t)r * QKVN + c8 * 8);
            uint4 vraw = *(const uint4*)(vsrc + (size_t)r * QKVN + c8 * 8);
            *(uint4*)(Ks + r * AK + c8 * 8) = kraw;
            *(uint4*)(Vs + r * AV + c8 * 8) = vraw;
        }
        if (tid < 64) mk[tid] = (mask[b * Ss + kt * 64 + tid] != 0) ? 1.f : 0.f;
        __syncthreads();

        // ---- scores: Q(16x64) . K^T  (fp16 mma, perm-k frags) ----
        float c[8][4];
        #pragma unroll
        for (int nt = 0; nt < 8; nt++)
            #pragma unroll
            for (int r = 0; r < 4; r++) c[nt][r] = 0.f;
        #pragma unroll
        for (int ks = 0; ks < 4; ks++) {
            const __half* qp = Qs + (warpM + rq) * AQ + ks * 16 + 4 * qd;
            uint2 lo = *(const uint2*)qp;
            uint2 hi = *(const uint2*)(qp + 8 * AQ);
            uint32_t a[4];
            a[0] = lo.x; a[1] = hi.x; a[2] = lo.y; a[3] = hi.y;
            #pragma unroll
            for (int nt = 0; nt < 8; nt++) {
                const __half* kp = Ks + (nt * 8 + rq) * AK + ks * 16 + 4 * qd;
                uint2 v = *(const uint2*)kp;
                uint32_t bfr[2];
                bfr[0] = v.x; bfr[1] = v.y;
                mma_f16(c[nt], a, bfr);
            }
        }

        // ---- mask + online softmax (fp32) ----
        float rmax0 = -1e30f, rmax1 = -1e30f;
        #pragma unroll
        for (int nt = 0; nt < 8; nt++) {
            int j0 = nt * 8 + 2 * qd;
            float mk0 = mk[j0], mk1 = mk[j0 + 1];
            if (mk0 != 0.f) { c[nt][0] = -1e9f; c[nt][2] = -1e9f; }
            if (mk1 != 0.f) { c[nt][1] = -1e9f; c[nt][3] = -1e9f; }
            rmax0 = fmaxf(rmax0, fmaxf(c[nt][0], c[nt][1]));
            rmax1 = fmaxf(rmax1, fmaxf(c[nt][2], c[nt][3]));
        }
        rmax0 = fmaxf(rmax0, __shfl_xor_sync(0xffffffffu, rmax0, 1));
        rmax0 = fmaxf(rmax0, __shfl_xor_sync(0xffffffffu, rmax0, 2));
        rmax1 = fmaxf(rmax1, __shfl_xor_sync(0xffffffffu, rmax1, 1));
        rmax1 = fmaxf(rmax1, __shfl_xor_sync(0xffffffffu, rmax1, 2));
        float mn0 = fmaxf(m0, rmax0), mn1 = fmaxf(m1, rmax1);
        float cor0 = __expf(m0 - mn0), cor1 = __expf(m1 - mn1);
        m0 = mn0; m1 = mn1;
        l0 *= cor0; l1 *= cor1;
        #pragma unroll
        for (int nt = 0; nt < 8; nt++) {
            oacc[nt][0] *= cor0; oacc[nt][1] *= cor0;
            oacc[nt][2] *= cor1; oacc[nt][3] *= cor1;
        }
        // exp + store P (half, natural cols), accumulate row sums
        #pragma unroll
        for (int nt = 0; nt < 8; nt++) {
            float p0 = __expf(c[nt][0] - m0);
            float p1 = __expf(c[nt][1] - m0);
            float p2 = __expf(c[nt][2] - m1);
            float p3 = __expf(c[nt][3] - m1);
            l0 += p0 + p1; l1 += p2 + p3;
            __half* pp = Ps + (warpM + rq) * AP + nt * 8 + 2 * qd;
            *(__half2*)pp            = __floats2half2_rn(p0, p1);
            *(__half2*)(pp + 8 * AP) = __floats2half2_rn(p2, p3);
        }
        __syncwarp();

        // ---- P.V: natural-k P frags + ldmatrix.trans V frags ----
        #pragma unroll
        for (int ks = 0; ks < 4; ks++) {
            const __half* pa = Ps + (warpM + rq) * AP + ks * 16 + 2 * qd;
            uint32_t a[4];
            a[0] = *(const uint32_t*)pa;
            a[1] = *(const uint32_t*)(pa + 8 * AP);
            a[2] = *(const uint32_t*)(pa + 8);
            a[3] = *(const uint32_t*)(pa + 8 * AP + 8);
            #pragma unroll
            for (int t = 0; t < 4; t++) {
                // 4 matrices: (k blk0,n 2t)(k blk1,n 2t)(k blk0,n 2t+1)(k blk1,n 2t+1)
                int vrow = ks * 16 + ((lane >> 3) & 1) * 8 + (lane & 7);
                int vcol = (2 * t + (lane >> 4)) * 8;
                uint32_t vaddr = vsb + (uint32_t)((vrow * AV + vcol) * 2);
                uint32_t r0, r1, r2, r3;
                LDSM_X4_TRANS(r0, r1, r2, r3, vaddr);
                uint32_t b0[2] = {r0, r1};
                uint32_t b1[2] = {r2, r3};
                mma_f16(oacc[2 * t],     a, b0);
                mma_f16(oacc[2 * t + 1], a, b1);
            }
        }
    }

    // final: row sums across quad, normalize, write half (next GEMM A)
    l0 += __shfl_xor_sync(0xffffffffu, l0, 1);
    l0 += __shfl_xor_sync(0xffffffffu, l0, 2);
    l1 += __shfl_xor_sync(0xffffffffu, l1, 1);
    l1 += __shfl_xor_sync(0xffffffffu, l1, 2);
    float inv0 = 1.f / l0, inv1 = 1.f / l1;
    int row0 = base_q + warpM + rq;
    #pragma unroll
    for (int nt = 0; nt < 8; nt++) {
        int col = h * HDd + nt * 8 + 2 * qd;
        *(__half2*)(att + (size_t)row0 * Dd + col) =
            __floats2half2_rn(oacc[nt][0] * inv0, oacc[nt][1] * inv0);
        *(__half2*)(att + (size_t)(row0 + 8) * Dd + col) =
            __floats2half2_rn(oacc[nt][2] * inv1, oacc[nt][3] * inv1);
    }
}

// ---------------- pooled LN + classifier ----------------
__global__ __launch_bounds__(256)
void pooled_kernel(const float* __restrict__ x,
                   const float* __restrict__ hs,
                   const float* __restrict__ hb,
                   const float* __restrict__ cw,
                   const float* __restrict__ cb,
                   float* __restrict__ out)
{
    __shared__ float buf[16];
    int b = blockIdx.x;
    int t = threadIdx.x;
    const float* xr = x + (size_t)b * Ss * Dd;
    float v0 = xr[t], v1 = xr[t + 256], v2 = xr[t + 512];
    float sum = v0 + v1 + v2;
    float sq  = v0*v0 + v1*v1 + v2*v2;
    blockReduce2(sum, sq, buf);
    float mean = sum * (1.0f / Dd);
    float var  = sq * (1.0f / Dd) - mean * mean;
    float rstd = rsqrtf(var + LN_EPS);
    float h0 = (v0 - mean) * rstd * hs[t]       + hb[t];
    float h1 = (v1 - mean) * rstd * hs[t + 256] + hb[t + 256];
    float h2 = (v2 - mean) * rstd * hs[t + 512] + hb[t + 512];
    float p0 = h0 * cw[t * 2]     + h1 * cw[(t + 256) * 2]     + h2 * cw[(t + 512) * 2];
    float p1 = h0 * cw[t * 2 + 1] + h1 * cw[(t + 256) * 2 + 1] + h2 * cw[(t + 512) * 2 + 1];
    blockReduce2(p0, p1, buf);
    if (t == 0) {
        out[b * Cc + 0] = p0 + cb[0];
        out[b * Cc + 1] = p1 + cb[1];
    }
}

// ---------------- launcher ----------------
extern "C" void kernel_launch(void* const* d_in, const int* in_sizes, int n_in,
                              void* d_out, int out_size)
{
    const int*   ids    = (const int*)  d_in[0];
    const int*   mask   = (const int*)  d_in[1];
    const float* tok    = (const float*)d_in[2];
    const float* pos    = (const float*)d_in[3];
    const float* qkv_w  = (const float*)d_in[4];
    const float* qkv_b  = (const float*)d_in[5];
    const float* out_w  = (const float*)d_in[6];
    const float* out_b  = (const float*)d_in[7];
    const float* n1_s   = (const float*)d_in[8];
    const float* n1_b   = (const float*)d_in[9];
    const float* ff1_w  = (const float*)d_in[10];
    const float* ff1_b  = (const float*)d_in[11];
    const float* ff2_w  = (const float*)d_in[12];
    const float* ff2_b  = (const float*)d_in[13];
    const float* n2_s   = (const float*)d_in[14];
    const float* n2_b   = (const float*)d_in[15];
    const float* hln_s  = (const float*)d_in[16];
    const float* hln_b  = (const float*)d_in[17];
    const float* cls_w  = (const float*)d_in[18];
    const float* cls_b  = (const float*)d_in[19];
    float* out = (float*)d_out;

    float *x;
    __half *h, *qkvb, *attb, *ffb, *wt;
    cudaGetSymbolAddress((void**)&x,    g_x);
    cudaGetSymbolAddress((void**)&h,    g_h);
    cudaGetSymbolAddress((void**)&qkvb, g_qkv);
    cudaGetSymbolAddress((void**)&attb, g_att);
    cudaGetSymbolAddress((void**)&ffb,  g_ff);
    cudaGetSymbolAddress((void**)&wt,   g_wt);

    cudaFuncSetAttribute(attn_mma_kernel,  cudaFuncAttributeMaxDynamicSharedMemorySize, ATT_SMEM);
    cudaFuncSetAttribute(mma_gemm<768,1>,  cudaFuncAttributeMaxDynamicSharedMemorySize, GEMM_SMEM);
    cudaFuncSetAttribute(mma_gemm<768,0>,  cudaFuncAttributeMaxDynamicSharedMemorySize, GEMM_SMEM);
    cudaFuncSetAttribute(mma_gemm<3072,0>, cudaFuncAttributeMaxDynamicSharedMemorySize, GEMM_SMEM);

    int embed_total = Mrows * (Dd / 4);
    embed_kernel<<<(embed_total + 255) / 256, 256>>>(ids, tok, pos, x);

    for (int i = 0; i < Ll; i++) {
        // LN1 -> h (half)
        ln_kernel<<<Mrows, 256>>>(x, n1_s + i * Dd, n1_b + i * Dd, h);

        // qkv: h[8192,768] @ W[768,2304] -> half qkv
        transpose_h_kernel<<<dim3(QKVN / 32, Dd / 32), 256>>>(qkv_w + (size_t)i * Dd * QKVN, wt, Dd, QKVN);
        mma_gemm<768,1><<<dim3(QKVN / 128, Mrows / 128), 256, GEMM_SMEM>>>(
            h, wt, qkv_b + (size_t)i * QKVN, nullptr, qkvb, QKVN, 0);

        attn_mma_kernel<<<dim3(Ss / 128, Hh, Bb), 256, ATT_SMEM>>>(qkvb, mask, attb);

        // out proj + residual: x = x + att @ W (float out)
        transpose_h_kernel<<<dim3(Dd / 32, Dd / 32), 256>>>(out_w + (size_t)i * Dd * Dd, wt, Dd, Dd);
        mma_gemm<768,0><<<dim3(Dd / 128, Mrows / 128), 256, GEMM_SMEM>>>(
            attb, wt, out_b + (size_t)i * Dd, x, x, Dd, 0);

        // LN2 -> h
        ln_kernel<<<Mrows, 256>>>(x, n2_s + i * Dd, n2_b + i * Dd, h);

        // ff1 + relu -> half ffb
        transpose_h_kernel<<<dim3(DFf / 32, Dd / 32), 256>>>(ff1_w + (size_t)i * Dd * DFf, wt, Dd, DFf);
        mma_gemm<768,1><<<dim3(DFf / 128, Mrows / 128), 256, GEMM_SMEM>>>(
            h, wt, ff1_b + (size_t)i * DFf, nullptr, ffb, DFf, 1);

        // ff2 + residual (float out)
        transpose_h_kernel<<<dim3(Dd / 32, DFf / 32), 256>>>(ff2_w + (size_t)i * DFf * Dd, wt, DFf, Dd);
        mma_gemm<3072,0><<<dim3(Dd / 128, Mrows / 128), 256, GEMM_SMEM>>>(
            ffb, wt, ff2_b + (size_t)i * Dd, x, x, Dd, 0);
    }

    pooled_kernel<<<Bb, 256>>>(x, hln_s, hln_b, cls_w, cls_b, out);
}

// round 9
// speedup vs baseline: 2.7271x; 1.0053x over previous
#include <cuda_runtime.h>
#include <cuda_fp16.h>
#include <cstdint>
#include <math.h>

#define Bb   8
#define Ss   1024
#define Dd   768
#define Hh   12
#define HDd  64
#define Ll   6
#define DFf  3072
#define Cc   2
#define Mrows (Bb*Ss)      /* 8192 */
#define QKVN  (3*Dd)       /* 2304 */
#define LN_EPS 1e-5f

// ---------------- scratch (device globals: allocation-free) ----------------
__device__ float  g_x[Mrows*Dd];
__device__ __half g_h[Mrows*Dd];
__device__ __half g_qkv[Mrows*QKVN];
__device__ __half g_att[Mrows*Dd];
__device__ __half g_ff[Mrows*DFf];
__device__ __half g_wt[DFf*Dd];     // transposed half weights (max 3072*768)

// ======================= helpers =======================
__device__ __forceinline__ uint32_t smem_to_u32(const void* p) {
    uint32_t a;
    asm("{ .reg .u64 t; cvta.to.shared.u64 t, %1; cvt.u32.u64 %0, t; }" : "=r"(a) : "l"(p));
    return a;
}
#define CP_ASYNC16(dst, src) \
    asm volatile("cp.async.cg.shared.global [%0], [%1], 16;" :: "r"(dst), "l"(src) : "memory")
#define CP_COMMIT() asm volatile("cp.async.commit_group;" ::: "memory")
#define CP_WAIT0()  asm volatile("cp.async.wait_group 0;" ::: "memory")
#define CP_WAIT1()  asm volatile("cp.async.wait_group 1;" ::: "memory")

// fp16 inputs, fp32 accumulate
__device__ __forceinline__ void mma_f16(float* d, const uint32_t* a, const uint32_t* b) {
    asm volatile(
        "mma.sync.aligned.m16n8k16.row.col.f32.f16.f16.f32 "
        "{%0,%1,%2,%3}, {%4,%5,%6,%7}, {%8,%9}, {%0,%1,%2,%3};"
        : "+f"(d[0]), "+f"(d[1]), "+f"(d[2]), "+f"(d[3])
        : "r"(a[0]), "r"(a[1]), "r"(a[2]), "r"(a[3]), "r"(b[0]), "r"(b[1]));
}
// ldmatrix x4 (b16)
#define LDSM_X4(r0, r1, r2, r3, addr) \
    asm volatile("ldmatrix.sync.aligned.m8n8.x4.shared.b16 {%0,%1,%2,%3}, [%4];" \
        : "=r"(r0), "=r"(r1), "=r"(r2), "=r"(r3) : "r"(addr))
// ldmatrix x4 transposed (b16)
#define LDSM_X4_TRANS(r0, r1, r2, r3, addr) \
    asm volatile("ldmatrix.sync.aligned.m8n8.x4.trans.shared.b16 {%0,%1,%2,%3}, [%4];" \
        : "=r"(r0), "=r"(r1), "=r"(r2), "=r"(r3) : "r"(addr))

// ---------------- embed ----------------
__global__ void embed_kernel(const int* __restrict__ ids,
                             const float* __restrict__ tok,
                             const float* __restrict__ pos,
                             float* __restrict__ x)
{
    const float sc = 27.712812921102035f; // sqrt(768)
    int i = blockIdx.x * blockDim.x + threadIdx.x;
    int total = Mrows * (Dd / 4);
    if (i >= total) return;
    int row = i / (Dd / 4);
    int c4  = i - row * (Dd / 4);
    int s   = row & (Ss - 1);
    int id  = ids[row];
    const float4* t4 = (const float4*)tok;
    const float4* p4 = (const float4*)pos;
    float4 tv = t4[(size_t)id * (Dd/4) + c4];
    float4 pv = p4[(size_t)s  * (Dd/4) + c4];
    float4 o;
    o.x = (tv.x + pv.x) * sc;
    o.y = (tv.y + pv.y) * sc;
    o.z = (tv.z + pv.z) * sc;
    o.w = (tv.w + pv.w) * sc;
    ((float4*)x)[i] = o;
}

// ---------------- block reduce ----------------
__device__ __forceinline__ void blockReduce2(float& a, float& b, float* buf)
{
    #pragma unroll
    for (int o = 16; o; o >>= 1) {
        a += __shfl_xor_sync(0xffffffffu, a, o);
        b += __shfl_xor_sync(0xffffffffu, b, o);
    }
    int w = threadIdx.x >> 5;
    if ((threadIdx.x & 31) == 0) { buf[w] = a; buf[8 + w] = b; }
    __syncthreads();
    a = 0.f; b = 0.f;
    #pragma unroll
    for (int i = 0; i < 8; i++) { a += buf[i]; b += buf[8 + i]; }
    __syncthreads();
}

// ---------------- layernorm (half output: feeds GEMM A) ----------------
__global__ __launch_bounds__(256)
void ln_kernel(const float* __restrict__ x,
               const float* __restrict__ gs,
               const float* __restrict__ gb,
               __half* __restrict__ out)
{
    __shared__ float buf[16];
    int row = blockIdx.x;
    int t = threadIdx.x;
    const float* xr = x + (size_t)row * Dd;
    float v0 = xr[t], v1 = xr[t + 256], v2 = xr[t + 512];
    float sum = v0 + v1 + v2;
    float sq  = v0*v0 + v1*v1 + v2*v2;
    blockReduce2(sum, sq, buf);
    float mean = sum * (1.0f / Dd);
    float var  = sq * (1.0f / Dd) - mean * mean;
    float rstd = rsqrtf(var + LN_EPS);
    __half* orow = out + (size_t)row * Dd;
    orow[t]       = __float2half_rn((v0 - mean) * rstd * gs[t]       + gb[t]);
    orow[t + 256] = __float2half_rn((v1 - mean) * rstd * gs[t + 256] + gb[t + 256]);
    orow[t + 512] = __float2half_rn((v2 - mean) * rstd * gs[t + 512] + gb[t + 512]);
}

// ---------------- weight transpose to half: Wt[N,K] = h(W[K,N]^T) ----------
__global__ __launch_bounds__(256)
void transpose_h_kernel(const float* __restrict__ W, __half* __restrict__ Wt, int K, int N)
{
    __shared__ float t[32][33];
    int n0 = blockIdx.x * 32, k0 = blockIdx.y * 32;
    int x = threadIdx.x & 31, y = threadIdx.x >> 5; // 32x8
    #pragma unroll
    for (int i = 0; i < 32; i += 8)
        t[y + i][x] = W[(size_t)(k0 + y + i) * N + n0 + x];
    __syncthreads();
    #pragma unroll
    for (int i = 0; i < 32; i += 8)
        Wt[(size_t)(n0 + y + i) * K + k0 + x] = __float2half_rn(t[x][y + i]);
}

// ---------------- fp16 mma.sync GEMM (v4: swizzle + ldmatrix + 3-stage) ----
// C[M,N] = A[M,K] @ Bt[N,K]^T (+bias)(+res)(relu?), fp32 accumulate.
// BM=BN=128, BK=64 halves, 256 threads, warp grid 2x4 (warp 64x32).
// SMEM: exact 128B rows, XOR swizzle (chunk c at position c ^ (r&7)).
// Fragments via ldmatrix.x4 (canonical mapping). 3-stage cp.async, wait 1.
#define TILEB 16384                  /* bytes per operand tile (128x64h) */
#define STGB  (2*TILEB)              /* A+B per stage */
#define GEMM_SMEM (3*STGB)           /* 98304 bytes */

template<int K, int OUTH>
__global__ __launch_bounds__(256, 2)
void mma_gemm(const __half* __restrict__ A, const __half* __restrict__ Bt,
              const float* __restrict__ bias, const float* __restrict__ res,
              void* __restrict__ Cv, int N, int relu)
{
    extern __shared__ __half smh[];
    uint32_t sb = smem_to_u32(smh);
    int tid = threadIdx.x, lane = tid & 31, wid = tid >> 5;
    int rq = lane >> 2, qd = lane & 3;
    int warpM = (wid >> 2) * 64, warpN = (wid & 3) * 32;
    int m0 = blockIdx.y * 128, n0 = blockIdx.x * 128;
    const __half* Abase = A  + (size_t)m0 * K;
    const __half* Bbase = Bt + (size_t)n0 * K;
    constexpr int KI = K >> 6;

    float acc[4][4][4];
    #pragma unroll
    for (int mt = 0; mt < 4; mt++)
        #pragma unroll
        for (int nt = 0; nt < 4; nt++)
            #pragma unroll
            for (int r = 0; r < 4; r++) acc[mt][nt][r] = 0.f;

    // cp.async fill: per tile 128 rows x 8 chunks(16B); swizzled chunk pos c^(r&7)
    #define ISSUE_STAGE(I) do {                                                    \
        uint32_t _base = sb + (uint32_t)((I) % 3) * STGB;                          \
        int _k0 = (I) << 6;                                                         \
        _Pragma("unroll")                                                           \
        for (int _it = 0; _it < 4; _it++) {                                         \
            int _idx = _it * 256 + tid;                                             \
            int _r = _idx >> 3, _c = _idx & 7;                                      \
            uint32_t _sw = (uint32_t)(_r * 128 + ((_c ^ (_r & 7)) << 4));           \
            CP_ASYNC16(_base + _sw,         Abase + (size_t)_r * K + _k0 + _c * 8); \
            CP_ASYNC16(_base + TILEB + _sw, Bbase + (size_t)_r * K + _k0 + _c * 8); \
        }                                                                           \
    } while (0)

    ISSUE_STAGE(0); CP_COMMIT();
    ISSUE_STAGE(1); CP_COMMIT();

    // per-lane ldmatrix row/chunk geometry
    int laneR = lane & 15;          // row within 16-row frag
    int hiK   = lane >> 4;          // chunk select (k lo/hi 8-half block)
    int r7    = lane & 7;           // swizzle key (rows are 8-aligned per frag)
    uint32_t rowA[4], rowB[2], cs[4];
    #pragma unroll
    for (int mt = 0; mt < 4; mt++) rowA[mt] = (uint32_t)((warpM + mt * 16 + laneR) * 128);
    #pragma unroll
    for (int np = 0; np < 2; np++) rowB[np] = (uint32_t)(TILEB + (warpN + np * 16 + laneR) * 128);
    #pragma unroll
    for (int ks = 0; ks < 4; ks++) cs[ks] = (uint32_t)(((2 * ks + hiK) ^ r7) << 4);

    for (int i = 0; i < KI; i++) {
        CP_WAIT1();
        __syncthreads();
        if (i + 2 < KI) ISSUE_STAGE(i + 2);
        CP_COMMIT();   // empty group in tail keeps wait_group semantics

        uint32_t stb = sb + (uint32_t)(i % 3) * STGB;

        #pragma unroll
        for (int ks = 0; ks < 4; ks++) {
            uint32_t a[4][4];
            #pragma unroll
            for (int mt = 0; mt < 4; mt++)
                LDSM_X4(a[mt][0], a[mt][1], a[mt][2], a[mt][3], stb + rowA[mt] + cs[ks]);
            uint32_t b[4][2];
            #pragma unroll
            for (int np = 0; np < 2; np++) {
                uint32_t r0, r1, r2, r3;
                LDSM_X4(r0, r1, r2, r3, stb + rowB[np] + cs[ks]);
                b[np * 2 + 0][0] = r0; b[np * 2 + 0][1] = r2;
                b[np * 2 + 1][0] = r1; b[np * 2 + 1][1] = r3;
            }
            #pragma unroll
            for (int mt = 0; mt < 4; mt++)
                #pragma unroll
                for (int nt = 0; nt < 4; nt++)
                    mma_f16(acc[mt][nt], a[mt], b[nt]);
        }
    }

    // epilogue
    #pragma unroll
    for (int mt = 0; mt < 4; mt++) {
        int r0 = m0 + warpM + mt * 16 + rq;
        #pragma unroll
        for (int nt = 0; nt < 4; nt++) {
            int c0 = n0 + warpN + nt * 8 + qd * 2;
            float2 bv = *(const float2*)(bias + c0);
            float v0 = acc[mt][nt][0] + bv.x;
            float v1 = acc[mt][nt][1] + bv.y;
            float v2 = acc[mt][nt][2] + bv.x;
            float v3 = acc[mt][nt][3] + bv.y;
            if (res) {
                float2 q1 = *(const float2*)(res + (size_t)r0 * N + c0);
                float2 q2 = *(const float2*)(res + (size_t)(r0 + 8) * N + c0);
                v0 += q1.x; v1 += q1.y; v2 += q2.x; v3 += q2.y;
            }
            if (relu) {
                v0 = fmaxf(v0, 0.f); v1 = fmaxf(v1, 0.f);
                v2 = fmaxf(v2, 0.f); v3 = fmaxf(v3, 0.f);
            }
            if (OUTH) {
                __half* C = (__half*)Cv;
                *(__half2*)(C + (size_t)r0 * N + c0)       = __floats2half2_rn(v0, v1);
                *(__half2*)(C + (size_t)(r0 + 8) * N + c0) = __floats2half2_rn(v2, v3);
            } else {
                float* C = (float*)Cv;
                float2 o1; o1.x = v0; o1.y = v1;
                float2 o2; o2.x = v2; o2.y = v3;
                *(float2*)(C + (size_t)r0 * N + c0)       = o1;
                *(float2*)(C + (size_t)(r0 + 8) * N + c0) = o2;
            }
        }
    }
}

// ---------------- fp16 tensor-core flash attention (unchanged from R8) ----
#define AQ 80
#define AK 80
#define AV 72
#define AP 72
#define ATT_SMEM ((128*AQ + 64*AK + 64*AV + 128*AP) * 2 + 64 * 4)

__global__ __launch_bounds__(256, 2)
void attn_mma_kernel(const __half* __restrict__ qkv,
                     const int* __restrict__ mask,
                     __half* __restrict__ att)
{
    extern __shared__ __half smha[];
    __half* Qs = smha;                 // [128][80]
    __half* Ks = Qs + 128 * AQ;        // [64][80]
    __half* Vs = Ks + 64 * AK;         // [64][72] natural [kvrow][dim]
    __half* Ps = Vs + 64 * AV;         // [128][72]
    float*  mk = (float*)(Ps + 128 * AP);  // [64]
    uint32_t vsb = smem_to_u32(Vs);

    int qb = blockIdx.x, h = blockIdx.y, b = blockIdx.z;
    int tid = threadIdx.x, lane = tid & 31, wid = tid >> 5;
    int rq = lane >> 2, qd = lane & 3;
    int warpM = wid * 16;
    int base_q = b * Ss + qb * 128;

    const __half2 qscale = __float2half2_rn(0.125f);
    const __half* qsrc = qkv + (size_t)base_q * QKVN + h * 192;
    #pragma unroll
    for (int it = 0; it < 4; it++) {
        int idx = it * 256 + tid;
        int r = idx >> 3, c8 = idx & 7;
        uint4 raw = *(const uint4*)(qsrc + (size_t)r * QKVN + c8 * 8);
        __half2* hp = (__half2*)&raw;
        hp[0] = __hmul2(hp[0], qscale);
        hp[1] = __hmul2(hp[1], qscale);
        hp[2] = __hmul2(hp[2], qscale);
        hp[3] = __hmul2(hp[3], qscale);
        *(uint4*)(Qs + r * AQ + c8 * 8) = raw;
    }

    float oacc[8][4];
    #pragma unroll
    for (int nt = 0; nt < 8; nt++)
        #pragma unroll
        for (int r = 0; r < 4; r++) oacc[nt][r] = 0.f;
    float m0 = -1e30f, m1 = -1e30f, l0 = 0.f, l1 = 0.f;

    __syncthreads();

    for (int kt = 0; kt < Ss / 64; kt++) {
        if (kt) __syncthreads();
        const __half* ksrc = qkv + (size_t)(b * Ss + kt * 64) * QKVN + h * 192 + 64;
        const __half* vsrc = ksrc + 64;
        #pragma unroll
        for (int it = 0; it < 2; it++) {
            int idx = it * 256 + tid;
            int r = idx >> 3, c8 = idx & 7;
            uint4 kraw = *(const uint4*)(ksrc + (size_t)r * QKVN + c8 * 8);
            uint4 vraw = *(const uint4*)(vsrc + (size_t)r * QKVN + c8 * 8);
            *(uint4*)(Ks + r * AK + c8 * 8) = kraw;
            *(uint4*)(Vs + r * AV + c8 * 8) = vraw;
        }
        if (tid < 64) mk[tid] = (mask[b * Ss + kt * 64 + tid] != 0) ? 1.f : 0.f;
        __syncthreads();

        float c[8][4];
        #pragma unroll
        for (int nt = 0; nt < 8; nt++)
            #pragma unroll
            for (int r = 0; r < 4; r++) c[nt][r] = 0.f;
        #pragma unroll
        for (int ks = 0; ks < 4; ks++) {
            const __half* qp = Qs + (warpM + rq) * AQ + ks * 16 + 4 * qd;
            uint2 lo = *(const uint2*)qp;
            uint2 hi = *(const uint2*)(qp + 8 * AQ);
            uint32_t a[4];
            a[0] = lo.x; a[1] = hi.x; a[2] = lo.y; a[3] = hi.y;
            #pragma unroll
            for (int nt = 0; nt < 8; nt++) {
                const __half* kp = Ks + (nt * 8 + rq) * AK + ks * 16 + 4 * qd;
                uint2 v = *(const uint2*)kp;
                uint32_t bfr[2];
                bfr[0] = v.x; bfr[1] = v.y;
                mma_f16(c[nt], a, bfr);
            }
        }

        float rmax0 = -1e30f, rmax1 = -1e30f;
        #pragma unroll
        for (int nt = 0; nt < 8; nt++) {
            int j0 = nt * 8 + 2 * qd;
            float mk0 = mk[j0], mk1 = mk[j0 + 1];
            if (mk0 != 0.f) { c[nt][0] = -1e9f; c[nt][2] = -1e9f; }
            if (mk1 != 0.f) { c[nt][1] = -1e9f; c[nt][3] = -1e9f; }
            rmax0 = fmaxf(rmax0, fmaxf(c[nt][0], c[nt][1]));
            rmax1 = fmaxf(rmax1, fmaxf(c[nt][2], c[nt][3]));
        }
        rmax0 = fmaxf(rmax0, __shfl_xor_sync(0xffffffffu, rmax0, 1));
        rmax0 = fmaxf(rmax0, __shfl_xor_sync(0xffffffffu, rmax0, 2));
        rmax1 = fmaxf(rmax1, __shfl_xor_sync(0xffffffffu, rmax1, 1));
        rmax1 = fmaxf(rmax1, __shfl_xor_sync(0xffffffffu, rmax1, 2));
        float mn0 = fmaxf(m0, rmax0), mn1 = fmaxf(m1, rmax1);
        float cor0 = __expf(m0 - mn0), cor1 = __expf(m1 - mn1);
        m0 = mn0; m1 = mn1;
        l0 *= cor0; l1 *= cor1;
        #pragma unroll
        for (int nt = 0; nt < 8; nt++) {
            oacc[nt][0] *= cor0; oacc[nt][1] *= cor0;
            oacc[nt][2] *= cor1; oacc[nt][3] *= cor1;
        }
        #pragma unroll
        for (int nt = 0; nt < 8; nt++) {
            float p0 = __expf(c[nt][0] - m0);
            float p1 = __expf(c[nt][1] - m0);
            float p2 = __expf(c[nt][2] - m1);
            float p3 = __expf(c[nt][3] - m1);
            l0 += p0 + p1; l1 += p2 + p3;
            __half* pp = Ps + (warpM + rq) * AP + nt * 8 + 2 * qd;
            *(__half2*)pp            = __floats2half2_rn(p0, p1);
            *(__half2*)(pp + 8 * AP) = __floats2half2_rn(p2, p3);
        }
        __syncwarp();

        #pragma unroll
        for (int ks = 0; ks < 4; ks++) {
            const __half* pa = Ps + (warpM + rq) * AP + ks * 16 + 2 * qd;
            uint32_t a[4];
            a[0] = *(const uint32_t*)pa;
            a[1] = *(const uint32_t*)(pa + 8 * AP);
            a[2] = *(const uint32_t*)(pa + 8);
            a[3] = *(const uint32_t*)(pa + 8 * AP + 8);
            #pragma unroll
            for (int t = 0; t < 4; t++) {
                int vrow = ks * 16 + ((lane >> 3) & 1) * 8 + (lane & 7);
                int vcol = (2 * t + (lane >> 4)) * 8;
                uint32_t vaddr = vsb + (uint32_t)((vrow * AV + vcol) * 2);
                uint32_t r0, r1, r2, r3;
                LDSM_X4_TRANS(r0, r1, r2, r3, vaddr);
                uint32_t b0[2] = {r0, r1};
                uint32_t b1[2] = {r2, r3};
                mma_f16(oacc[2 * t],     a, b0);
                mma_f16(oacc[2 * t + 1], a, b1);
            }
        }
    }

    l0 += __shfl_xor_sync(0xffffffffu, l0, 1);
    l0 += __shfl_xor_sync(0xffffffffu, l0, 2);
    l1 += __shfl_xor_sync(0xffffffffu, l1, 1);
    l1 += __shfl_xor_sync(0xffffffffu, l1, 2);
    float inv0 = 1.f / l0, inv1 = 1.f / l1;
    int row0 = base_q + warpM + rq;
    #pragma unroll
    for (int nt = 0; nt < 8; nt++) {
        int col = h * HDd + nt * 8 + 2 * qd;
        *(__half2*)(att + (size_t)row0 * Dd + col) =
            __floats2half2_rn(oacc[nt][0] * inv0, oacc[nt][1] * inv0);
        *(__half2*)(att + (size_t)(row0 + 8) * Dd + col) =
            __floats2half2_rn(oacc[nt][2] * inv1, oacc[nt][3] * inv1);
    }
}

// ---------------- pooled LN + classifier ----------------
__global__ __launch_bounds__(256)
void pooled_kernel(const float* __restrict__ x,
                   const float* __restrict__ hs,
                   const float* __restrict__ hb,
                   const float* __restrict__ cw,
                   const float* __restrict__ cb,
                   float* __restrict__ out)
{
    __shared__ float buf[16];
    int b = blockIdx.x;
    int t = threadIdx.x;
    const float* xr = x + (size_t)b * Ss * Dd;
    float v0 = xr[t], v1 = xr[t + 256], v2 = xr[t + 512];
    float sum = v0 + v1 + v2;
    float sq  = v0*v0 + v1*v1 + v2*v2;
    blockReduce2(sum, sq, buf);
    float mean = sum * (1.0f / Dd);
    float var  = sq * (1.0f / Dd) - mean * mean;
    float rstd = rsqrtf(var + LN_EPS);
    float h0 = (v0 - mean) * rstd * hs[t]       + hb[t];
    float h1 = (v1 - mean) * rstd * hs[t + 256] + hb[t + 256];
    float h2 = (v2 - mean) * rstd * hs[t + 512] + hb[t + 512];
    float p0 = h0 * cw[t * 2]     + h1 * cw[(t + 256) * 2]     + h2 * cw[(t + 512) * 2];
    float p1 = h0 * cw[t * 2 + 1] + h1 * cw[(t + 256) * 2 + 1] + h2 * cw[(t + 512) * 2 + 1];
    blockReduce2(p0, p1, buf);
    if (t == 0) {
        out[b * Cc + 0] = p0 + cb[0];
        out[b * Cc + 1] = p1 + cb[1];
    }
}

// ---------------- launcher ----------------
extern "C" void kernel_launch(void* const* d_in, const int* in_sizes, int n_in,
                              void* d_out, int out_size)
{
    const int*   ids    = (const int*)  d_in[0];
    const int*   mask   = (const int*)  d_in[1];
    const float* tok    = (const float*)d_in[2];
    const float* pos    = (const float*)d_in[3];
    const float* qkv_w  = (const float*)d_in[4];
    const float* qkv_b  = (const float*)d_in[5];
    const float* out_w  = (const float*)d_in[6];
    const float* out_b  = (const float*)d_in[7];
    const float* n1_s   = (const float*)d_in[8];
    const float* n1_b   = (const float*)d_in[9];
    const float* ff1_w  = (const float*)d_in[10];
    const float* ff1_b  = (const float*)d_in[11];
    const float* ff2_w  = (const float*)d_in[12];
    const float* ff2_b  = (const float*)d_in[13];
    const float* n2_s   = (const float*)d_in[14];
    const float* n2_b   = (const float*)d_in[15];
    const float* hln_s  = (const float*)d_in[16];
    const float* hln_b  = (const float*)d_in[17];
    const float* cls_w  = (const float*)d_in[18];
    const float* cls_b  = (const float*)d_in[19];
    float* out = (float*)d_out;

    float *x;
    __half *h, *qkvb, *attb, *ffb, *wt;
    cudaGetSymbolAddress((void**)&x,    g_x);
    cudaGetSymbolAddress((void**)&h,    g_h);
    cudaGetSymbolAddress((void**)&qkvb, g_qkv);
    cudaGetSymbolAddress((void**)&attb, g_att);
    cudaGetSymbolAddress((void**)&ffb,  g_ff);
    cudaGetSymbolAddress((void**)&wt,   g_wt);

    cudaFuncSetAttribute(attn_mma_kernel,  cudaFuncAttributeMaxDynamicSharedMemorySize, ATT_SMEM);
    cudaFuncSetAttribute(mma_gemm<768,1>,  cudaFuncAttributeMaxDynamicSharedMemorySize, GEMM_SMEM);
    cudaFuncSetAttribute(mma_gemm<768,0>,  cudaFuncAttributeMaxDynamicSharedMemorySize, GEMM_SMEM);
    cudaFuncSetAttribute(mma_gemm<3072,0>, cudaFuncAttributeMaxDynamicSharedMemorySize, GEMM_SMEM);

    int embed_total = Mrows * (Dd / 4);
    embed_kernel<<<(embed_total + 255) / 256, 256>>>(ids, tok, pos, x);

    for (int i = 0; i < Ll; i++) {
        // LN1 -> h (half)
        ln_kernel<<<Mrows, 256>>>(x, n1_s + i * Dd, n1_b + i * Dd, h);

        // qkv: h[8192,768] @ W[768,2304] -> half qkv
        transpose_h_kernel<<<dim3(QKVN / 32, Dd / 32), 256>>>(qkv_w + (size_t)i * Dd * QKVN, wt, Dd, QKVN);
        mma_gemm<768,1><<<dim3(QKVN / 128, Mrows / 128), 256, GEMM_SMEM>>>(
            h, wt, qkv_b + (size_t)i * QKVN, nullptr, qkvb, QKVN, 0);

        attn_mma_kernel<<<dim3(Ss / 128, Hh, Bb), 256, ATT_SMEM>>>(qkvb, mask, attb);

        // out proj + residual: x = x + att @ W (float out)
        transpose_h_kernel<<<dim3(Dd / 32, Dd / 32), 256>>>(out_w + (size_t)i * Dd * Dd, wt, Dd, Dd);
        mma_gemm<768,0><<<dim3(Dd / 128, Mrows / 128), 256, GEMM_SMEM>>>(
            attb, wt, out_b + (size_t)i * Dd, x, x, Dd, 0);

        // LN2 -> h
        ln_kernel<<<Mrows, 256>>>(x, n2_s + i * Dd, n2_b + i * Dd, h);

        // ff1 + relu -> half ffb
        transpose_h_kernel<<<dim3(DFf / 32, Dd / 32), 256>>>(ff1_w + (size_t)i * Dd * DFf, wt, Dd, DFf);
        mma_gemm<768,1><<<dim3(DFf / 128, Mrows / 128), 256, GEMM_SMEM>>>(
            h, wt, ff1_b + (size_t)i * DFf, nullptr, ffb, DFf, 1);

        // ff2 + residual (float out)
        transpose_h_kernel<<<dim3(Dd / 32, DFf / 32), 256>>>(ff2_w + (size_t)i * DFf * Dd, wt, DFf, Dd);
        mma_gemm<3072,0><<<dim3(Dd / 128, Mrows / 128), 256, GEMM_SMEM>>>(
            ffb, wt, ff2_b + (size_t)i * Dd, x, x, Dd, 0);
    }

    pooled_kernel<<<Bb, 256>>>(x, hln_s, hln_b, cls_w, cls_b, out);
}